// round 1
// baseline (speedup 1.0000x reference)
#include <cuda_runtime.h>
#include <math.h>

// TriangleMultiplication: N=768, C=128
// pipeline:
//   k_ln1      : x = LN(pair)                       -> g_x [r][c]
//   k_projgate : a,b = split((x@Wp^T)*mask*sig(x@Wg^T)) -> g_a,g_b [c][i][k] (channel-major)
//   k_einsum   : out_c = A_c @ B_c^T per channel     -> g_o [c][i][j]
//   k_ln2t     : u = LN_c(out) transposed            -> g_u (=g_a reuse) [r][c]
//   k_final    : out = (u@Wo^T) * sig(x@Wgat^T)      -> d_out [r][c]

#define NTOK 768
#define CH   128
#define RTOT (NTOK*NTOK)   // 589824

__device__ float g_x[(size_t)RTOT*CH];
__device__ float g_a[(size_t)CH*RTOT];
__device__ float g_b[(size_t)CH*RTOT];
__device__ float g_o[(size_t)CH*RTOT];

__device__ __forceinline__ float sigm(float v){ return 1.f/(1.f+expf(-v)); }

// ---------------------------------------------------------------- LN1
// one warp per row of 128; 8 rows per block
__global__ void k_ln1(const float* __restrict__ pair,
                      const float* __restrict__ w,
                      const float* __restrict__ b)
{
    int warp = threadIdx.x >> 5, lane = threadIdx.x & 31;
    size_t r = (size_t)blockIdx.x * 8 + warp;
    const float4* src = (const float4*)(pair + r * CH);
    float4 v = src[lane];
    float s = v.x + v.y + v.z + v.w;
    #pragma unroll
    for (int o = 16; o; o >>= 1) s += __shfl_xor_sync(0xffffffffu, s, o);
    float mu = s * (1.f/128.f);
    float dx = v.x-mu, dy = v.y-mu, dz = v.z-mu, dw = v.w-mu;
    float q = dx*dx + dy*dy + dz*dz + dw*dw;
    #pragma unroll
    for (int o = 16; o; o >>= 1) q += __shfl_xor_sync(0xffffffffu, q, o);
    float rstd = rsqrtf(q * (1.f/128.f) + 1e-5f);
    float4 wv = ((const float4*)w)[lane];
    float4 bv = ((const float4*)b)[lane];
    float4 o4;
    o4.x = dx*rstd*wv.x + bv.x;
    o4.y = dy*rstd*wv.y + bv.y;
    o4.z = dz*rstd*wv.z + bv.z;
    o4.w = dw*rstd*wv.w + bv.w;
    ((float4*)(g_x + r * CH))[lane] = o4;
}

// ---------------------------------------------------------------- proj+gate
// block: 32 rows x 512 cols, k=128, 256 threads, thread tile 8x8.
// col order j = 4c+q : q0=proj[2c], q1=proj[2c+1], q2=gate[2c], q3=gate[2c+1]
// epilogue: a[c]=p0*mask*sig(g0), b[c]=p1*mask*sig(g1); staged to smem,
// written channel-major to g_a/g_b.
__global__ void k_projgate(const float* __restrict__ projw,
                           const float* __restrict__ gatew,
                           const float* __restrict__ mask)
{
    __shared__ float sm[16*36 + 16*520];   // Xs[16][36] | Ws[16][520]
    float* Xs = sm;
    float* Ws = sm + 16*36;

    int tid = threadIdx.x;
    size_t r0 = (size_t)blockIdx.x * 32;
    int rg = tid >> 6;            // 0..3
    int jg = tid & 63;            // 0..63
    int r0l = rg * 8, j0 = jg * 8;

    float acc[8][8];
    #pragma unroll
    for (int i = 0; i < 8; i++)
        #pragma unroll
        for (int j = 0; j < 8; j++) acc[i][j] = 0.f;

    const float* X = g_x + r0 * CH;

    for (int k0 = 0; k0 < CH; k0 += 16) {
        __syncthreads();
        if (tid < 128) {
            int rr = tid >> 2, kq = tid & 3;
            float4 v = *(const float4*)(X + (size_t)rr*CH + k0 + kq*4);
            Xs[(kq*4+0)*36 + rr] = v.x;
            Xs[(kq*4+1)*36 + rr] = v.y;
            Xs[(kq*4+2)*36 + rr] = v.z;
            Xs[(kq*4+3)*36 + rr] = v.w;
        }
        #pragma unroll
        for (int l = 0; l < 8; l++) {
            int f = tid + l*256;          // 0..2047 float4s
            int j = f >> 2, kq = f & 3;
            int c = j >> 2, q = j & 3;
            const float* wsrc = (q < 2) ? (projw + (size_t)(2*c+q)*CH)
                                        : (gatew + (size_t)(2*c+q-2)*CH);
            float4 v = *(const float4*)(wsrc + k0 + kq*4);
            Ws[(kq*4+0)*520 + j] = v.x;
            Ws[(kq*4+1)*520 + j] = v.y;
            Ws[(kq*4+2)*520 + j] = v.z;
            Ws[(kq*4+3)*520 + j] = v.w;
        }
        __syncthreads();
        #pragma unroll
        for (int kk = 0; kk < 16; kk++) {
            float xf[8], wf[8];
            *(float4*)(xf)   = *(const float4*)(&Xs[kk*36 + r0l]);
            *(float4*)(xf+4) = *(const float4*)(&Xs[kk*36 + r0l + 4]);
            *(float4*)(wf)   = *(const float4*)(&Ws[kk*520 + j0]);
            *(float4*)(wf+4) = *(const float4*)(&Ws[kk*520 + j0 + 4]);
            #pragma unroll
            for (int i = 0; i < 8; i++)
                #pragma unroll
                for (int j = 0; j < 8; j++)
                    acc[i][j] += xf[i] * wf[j];
        }
    }

    __syncthreads();
    float* a_s = sm;           // [128][33]
    float* b_s = sm + 4224;
    int c0 = j0 >> 2;
    #pragma unroll
    for (int ri = 0; ri < 8; ri++) {
        int rl = r0l + ri;
        float mk = mask[(int)((r0 + rl) % NTOK)];
        #pragma unroll
        for (int h = 0; h < 2; h++) {
            int c = c0 + h;
            float p0 = acc[ri][h*4+0], p1 = acc[ri][h*4+1];
            float g0 = acc[ri][h*4+2], g1 = acc[ri][h*4+3];
            a_s[c*33 + rl] = p0 * mk * sigm(g0);
            b_s[c*33 + rl] = p1 * mk * sigm(g1);
        }
    }
    __syncthreads();
    for (int idx = tid; idx < CH*32; idx += 256) {
        int c = idx >> 5, rr = idx & 31;
        g_a[(size_t)c*RTOT + r0 + rr] = a_s[c*33 + rr];
        g_b[(size_t)c*RTOT + r0 + rr] = b_s[c*33 + rr];
    }
}

// ---------------------------------------------------------------- per-channel NT SGEMM
// out_c[i][j] = sum_k A_c[i][k]*B_c[j][k]; 128x128 block tile, k-chunk 32,
// 256 threads, 8x8 register tile.
__global__ void k_einsum()
{
    __shared__ float As[32*132];
    __shared__ float Bs[32*132];
    int c = blockIdx.z;
    const float* A = g_a + (size_t)c * RTOT;
    const float* B = g_b + (size_t)c * RTOT;
    float*       O = g_o + (size_t)c * RTOT;
    int i0 = blockIdx.y * 128, j0 = blockIdx.x * 128;
    int tid = threadIdx.x;
    int tr = tid >> 4, tc = tid & 15;
    int row0 = tr * 8, col0 = tc * 8;

    float acc[8][8];
    #pragma unroll
    for (int i = 0; i < 8; i++)
        #pragma unroll
        for (int j = 0; j < 8; j++) acc[i][j] = 0.f;

    for (int k0 = 0; k0 < NTOK; k0 += 32) {
        __syncthreads();
        #pragma unroll
        for (int l = 0; l < 4; l++) {
            int f = tid + l*256;          // 0..1023 float4s
            int rr = f >> 3, kq = f & 7;
            float4 va = *(const float4*)(A + (size_t)(i0+rr)*NTOK + k0 + kq*4);
            As[(kq*4+0)*132 + rr] = va.x;
            As[(kq*4+1)*132 + rr] = va.y;
            As[(kq*4+2)*132 + rr] = va.z;
            As[(kq*4+3)*132 + rr] = va.w;
            float4 vb = *(const float4*)(B + (size_t)(j0+rr)*NTOK + k0 + kq*4);
            Bs[(kq*4+0)*132 + rr] = vb.x;
            Bs[(kq*4+1)*132 + rr] = vb.y;
            Bs[(kq*4+2)*132 + rr] = vb.z;
            Bs[(kq*4+3)*132 + rr] = vb.w;
        }
        __syncthreads();
        #pragma unroll
        for (int kk = 0; kk < 32; kk++) {
            float af[8], bf[8];
            *(float4*)(af)   = *(const float4*)(&As[kk*132 + row0]);
            *(float4*)(af+4) = *(const float4*)(&As[kk*132 + row0 + 4]);
            *(float4*)(bf)   = *(const float4*)(&Bs[kk*132 + col0]);
            *(float4*)(bf+4) = *(const float4*)(&Bs[kk*132 + col0 + 4]);
            #pragma unroll
            for (int i = 0; i < 8; i++)
                #pragma unroll
                for (int j = 0; j < 8; j++)
                    acc[i][j] += af[i] * bf[j];
        }
    }

    #pragma unroll
    for (int ri = 0; ri < 8; ri++) {
        float* dst = O + (size_t)(i0 + row0 + ri)*NTOK + j0 + col0;
        float4 v0, v1;
        v0.x = acc[ri][0]; v0.y = acc[ri][1]; v0.z = acc[ri][2]; v0.w = acc[ri][3];
        v1.x = acc[ri][4]; v1.y = acc[ri][5]; v1.z = acc[ri][6]; v1.w = acc[ri][7];
        *(float4*)dst = v0;
        *(float4*)(dst + 4) = v1;
    }
}

// ---------------------------------------------------------------- LN2 + transpose
// block handles 32 consecutive r=(i,j); reads g_o[c][r] tiles, LN over c,
// writes g_u (=g_a) row-major [r][c].
__global__ void k_ln2t(const float* __restrict__ w, const float* __restrict__ b)
{
    __shared__ float t[128*33];
    __shared__ float red[8][33];
    __shared__ float mu_s[32], rstd_s[32];
    int tid = threadIdx.x;
    size_t r0 = (size_t)blockIdx.x * 32;

    for (int idx = tid; idx < CH*32; idx += 256) {
        int c = idx >> 5, rr = idx & 31;
        t[c*33 + rr] = g_o[(size_t)c*RTOT + r0 + rr];
    }
    __syncthreads();
    int rr = tid & 31, part = tid >> 5;
    float s = 0.f;
    for (int c = part*16; c < part*16 + 16; c++) s += t[c*33 + rr];
    red[part][rr] = s;
    __syncthreads();
    if (tid < 32) {
        float tot = 0.f;
        #pragma unroll
        for (int p = 0; p < 8; p++) tot += red[p][tid];
        mu_s[tid] = tot * (1.f/128.f);
    }
    __syncthreads();
    float mu = mu_s[rr], q = 0.f;
    for (int c = part*16; c < part*16 + 16; c++) {
        float d = t[c*33 + rr] - mu; q += d*d;
    }
    __syncthreads();
    red[part][rr] = q;
    __syncthreads();
    if (tid < 32) {
        float tot = 0.f;
        #pragma unroll
        for (int p = 0; p < 8; p++) tot += red[p][tid];
        rstd_s[tid] = rsqrtf(tot * (1.f/128.f) + 1e-5f);
    }
    __syncthreads();
    float* u = g_a;   // g_a is dead: reuse as u buffer
    for (int idx = tid; idx < CH*32; idx += 256) {
        int rr2 = idx >> 7, c = idx & 127;
        float val = (t[c*33 + rr2] - mu_s[rr2]) * rstd_s[rr2] * w[c] + b[c];
        u[(r0 + rr2)*CH + c] = val;
    }
}

// ---------------------------------------------------------------- final fused GEMM
// block: 64 rows x 256 cols (col j = 2c+q: q0 -> out_w row c applied to u,
// q1 -> gating_w row c applied to x). 256 threads, thread tile 8x8.
// out[r][c] = dot(u,out_w[c]) * sig(dot(x,gating_w[c]))
__global__ void k_final(const float* __restrict__ outw,
                        const float* __restrict__ gatingw,
                        float* __restrict__ out)
{
    __shared__ float Us[16*68];
    __shared__ float Xs[16*68];
    __shared__ float Ws[16*260];
    int tid = threadIdx.x;
    size_t r0 = (size_t)blockIdx.x * 64;
    int rg = tid >> 5;            // 0..7
    int jg = tid & 31;            // 0..31
    int r0l = rg * 8, j0 = jg * 8;

    const float* U = g_a + r0 * CH;
    const float* X = g_x + r0 * CH;

    float acc[8][8];
    #pragma unroll
    for (int i = 0; i < 8; i++)
        #pragma unroll
        for (int j = 0; j < 8; j++) acc[i][j] = 0.f;

    for (int k0 = 0; k0 < CH; k0 += 16) {
        __syncthreads();
        {   // U and X tiles: 64 rows x 16 = 256 float4 each
            int rr = tid >> 2, kq = tid & 3;
            float4 vu = *(const float4*)(U + (size_t)rr*CH + k0 + kq*4);
            Us[(kq*4+0)*68 + rr] = vu.x;
            Us[(kq*4+1)*68 + rr] = vu.y;
            Us[(kq*4+2)*68 + rr] = vu.z;
            Us[(kq*4+3)*68 + rr] = vu.w;
            float4 vx = *(const float4*)(X + (size_t)rr*CH + k0 + kq*4);
            Xs[(kq*4+0)*68 + rr] = vx.x;
            Xs[(kq*4+1)*68 + rr] = vx.y;
            Xs[(kq*4+2)*68 + rr] = vx.z;
            Xs[(kq*4+3)*68 + rr] = vx.w;
        }
        #pragma unroll
        for (int l = 0; l < 4; l++) {     // W tile: 256 x 16 = 1024 float4
            int f = tid + l*256;
            int j = f >> 2, kq = f & 3;
            int c = j >> 1, q = j & 1;
            const float* wsrc = q ? (gatingw + (size_t)c*CH) : (outw + (size_t)c*CH);
            float4 v = *(const float4*)(wsrc + k0 + kq*4);
            Ws[(kq*4+0)*260 + j] = v.x;
            Ws[(kq*4+1)*260 + j] = v.y;
            Ws[(kq*4+2)*260 + j] = v.z;
            Ws[(kq*4+3)*260 + j] = v.w;
        }
        __syncthreads();
        #pragma unroll
        for (int kk = 0; kk < 16; kk++) {
            float uf[8], xf[8];
            *(float4*)(uf)   = *(const float4*)(&Us[kk*68 + r0l]);
            *(float4*)(uf+4) = *(const float4*)(&Us[kk*68 + r0l + 4]);
            *(float4*)(xf)   = *(const float4*)(&Xs[kk*68 + r0l]);
            *(float4*)(xf+4) = *(const float4*)(&Xs[kk*68 + r0l + 4]);
            #pragma unroll
            for (int jj = 0; jj < 8; jj++) {
                float wv = Ws[kk*260 + j0 + jj];
                if (jj & 1) {
                    #pragma unroll
                    for (int i = 0; i < 8; i++) acc[i][jj] += xf[i] * wv;
                } else {
                    #pragma unroll
                    for (int i = 0; i < 8; i++) acc[i][jj] += uf[i] * wv;
                }
            }
        }
    }

    int co0 = j0 >> 1;   // 4 consecutive output channels
    #pragma unroll
    for (int ri = 0; ri < 8; ri++) {
        size_t r = r0 + r0l + ri;
        float4 o;
        o.x = acc[ri][0] * sigm(acc[ri][1]);
        o.y = acc[ri][2] * sigm(acc[ri][3]);
        o.z = acc[ri][4] * sigm(acc[ri][5]);
        o.w = acc[ri][6] * sigm(acc[ri][7]);
        *(float4*)(out + r*CH + co0) = o;
    }
}

// ---------------------------------------------------------------- launch
extern "C" void kernel_launch(void* const* d_in, const int* in_sizes, int n_in,
                              void* d_out, int out_size)
{
    const float* pair     = (const float*)d_in[0];
    const float* mask     = (const float*)d_in[1];
    const float* ln1_w    = (const float*)d_in[2];
    const float* ln1_b    = (const float*)d_in[3];
    const float* proj_w   = (const float*)d_in[4];
    const float* gate_w   = (const float*)d_in[5];
    const float* ln2_w    = (const float*)d_in[6];
    const float* ln2_b    = (const float*)d_in[7];
    const float* out_w    = (const float*)d_in[8];
    const float* gating_w = (const float*)d_in[9];
    float* out = (float*)d_out;

    k_ln1<<<RTOT/8, 256>>>(pair, ln1_w, ln1_b);
    k_projgate<<<RTOT/32, 256>>>(proj_w, gate_w, mask);
    k_einsum<<<dim3(NTOK/128, NTOK/128, CH), 256>>>();
    k_ln2t<<<RTOT/32, 256>>>(ln2_w, ln2_b);
    k_final<<<RTOT/64, 256>>>(out_w, gating_w, out);
}

// round 2
// speedup vs baseline: 1.0006x; 1.0006x over previous
#include <cuda_runtime.h>
#include <math.h>

// TriangleMultiplication: N=768, C=128
// pipeline:
//   k_ln1      : x = LN(pair)                       -> g_x [r][c]
//   k_projgate : a,b = split((x@Wp^T)*mask*sig(x@Wg^T)) -> g_a,g_b [c][i][k] (channel-major)
//   k_einsum   : out_c = A_c @ B_c^T per channel     -> g_o [c][i][j]
//   k_ln2t     : u = LN_c(out) transposed            -> g_u (=g_a reuse) [r][c]
//   k_final    : out = (u@Wo^T) * sig(x@Wgat^T)      -> d_out [r][c]

#define NTOK 768
#define CH   128
#define RTOT (NTOK*NTOK)   // 589824

__device__ float g_x[(size_t)RTOT*CH];
__device__ float g_a[(size_t)CH*RTOT];
__device__ float g_b[(size_t)CH*RTOT];
__device__ float g_o[(size_t)CH*RTOT];

__device__ __forceinline__ float sigm(float v){ return 1.f/(1.f+expf(-v)); }

// ---------------------------------------------------------------- LN1
// one warp per row of 128; 8 rows per block
__global__ void k_ln1(const float* __restrict__ pair,
                      const float* __restrict__ w,
                      const float* __restrict__ b)
{
    int warp = threadIdx.x >> 5, lane = threadIdx.x & 31;
    size_t r = (size_t)blockIdx.x * 8 + warp;
    const float4* src = (const float4*)(pair + r * CH);
    float4 v = src[lane];
    float s = v.x + v.y + v.z + v.w;
    #pragma unroll
    for (int o = 16; o; o >>= 1) s += __shfl_xor_sync(0xffffffffu, s, o);
    float mu = s * (1.f/128.f);
    float dx = v.x-mu, dy = v.y-mu, dz = v.z-mu, dw = v.w-mu;
    float q = dx*dx + dy*dy + dz*dz + dw*dw;
    #pragma unroll
    for (int o = 16; o; o >>= 1) q += __shfl_xor_sync(0xffffffffu, q, o);
    float rstd = rsqrtf(q * (1.f/128.f) + 1e-5f);
    float4 wv = ((const float4*)w)[lane];
    float4 bv = ((const float4*)b)[lane];
    float4 o4;
    o4.x = dx*rstd*wv.x + bv.x;
    o4.y = dy*rstd*wv.y + bv.y;
    o4.z = dz*rstd*wv.z + bv.z;
    o4.w = dw*rstd*wv.w + bv.w;
    ((float4*)(g_x + r * CH))[lane] = o4;
}

// ---------------------------------------------------------------- proj+gate
// block: 32 rows x 512 cols, k=128, 256 threads, thread tile 8x8.
// col order j = 4c+q : q0=proj[2c], q1=proj[2c+1], q2=gate[2c], q3=gate[2c+1]
// epilogue: a[c]=p0*mask*sig(g0), b[c]=p1*mask*sig(g1); staged to smem,
// written channel-major to g_a/g_b.
__global__ void k_projgate(const float* __restrict__ projw,
                           const float* __restrict__ gatew,
                           const float* __restrict__ mask)
{
    __shared__ float sm[16*36 + 16*520];   // Xs[16][36] | Ws[16][520]
    float* Xs = sm;
    float* Ws = sm + 16*36;

    int tid = threadIdx.x;
    size_t r0 = (size_t)blockIdx.x * 32;
    int rg = tid >> 6;            // 0..3
    int jg = tid & 63;            // 0..63
    int r0l = rg * 8, j0 = jg * 8;

    float acc[8][8];
    #pragma unroll
    for (int i = 0; i < 8; i++)
        #pragma unroll
        for (int j = 0; j < 8; j++) acc[i][j] = 0.f;

    const float* X = g_x + r0 * CH;

    for (int k0 = 0; k0 < CH; k0 += 16) {
        __syncthreads();
        if (tid < 128) {
            int rr = tid >> 2, kq = tid & 3;
            float4 v = *(const float4*)(X + (size_t)rr*CH + k0 + kq*4);
            Xs[(kq*4+0)*36 + rr] = v.x;
            Xs[(kq*4+1)*36 + rr] = v.y;
            Xs[(kq*4+2)*36 + rr] = v.z;
            Xs[(kq*4+3)*36 + rr] = v.w;
        }
        #pragma unroll
        for (int l = 0; l < 8; l++) {
            int f = tid + l*256;          // 0..2047 float4s
            int j = f >> 2, kq = f & 3;
            int c = j >> 2, q = j & 3;
            const float* wsrc = (q < 2) ? (projw + (size_t)(2*c+q)*CH)
                                        : (gatew + (size_t)(2*c+q-2)*CH);
            float4 v = *(const float4*)(wsrc + k0 + kq*4);
            Ws[(kq*4+0)*520 + j] = v.x;
            Ws[(kq*4+1)*520 + j] = v.y;
            Ws[(kq*4+2)*520 + j] = v.z;
            Ws[(kq*4+3)*520 + j] = v.w;
        }
        __syncthreads();
        #pragma unroll
        for (int kk = 0; kk < 16; kk++) {
            float xf[8], wf[8];
            *(float4*)(xf)   = *(const float4*)(&Xs[kk*36 + r0l]);
            *(float4*)(xf+4) = *(const float4*)(&Xs[kk*36 + r0l + 4]);
            *(float4*)(wf)   = *(const float4*)(&Ws[kk*520 + j0]);
            *(float4*)(wf+4) = *(const float4*)(&Ws[kk*520 + j0 + 4]);
            #pragma unroll
            for (int i = 0; i < 8; i++)
                #pragma unroll
                for (int j = 0; j < 8; j++)
                    acc[i][j] += xf[i] * wf[j];
        }
    }

    __syncthreads();
    float* a_s = sm;           // [128][33]
    float* b_s = sm + 4224;
    int c0 = j0 >> 2;
    #pragma unroll
    for (int ri = 0; ri < 8; ri++) {
        int rl = r0l + ri;
        float mk = mask[(int)((r0 + rl) % NTOK)];
        #pragma unroll
        for (int h = 0; h < 2; h++) {
            int c = c0 + h;
            float p0 = acc[ri][h*4+0], p1 = acc[ri][h*4+1];
            float g0 = acc[ri][h*4+2], g1 = acc[ri][h*4+3];
            a_s[c*33 + rl] = p0 * mk * sigm(g0);
            b_s[c*33 + rl] = p1 * mk * sigm(g1);
        }
    }
    __syncthreads();
    for (int idx = tid; idx < CH*32; idx += 256) {
        int c = idx >> 5, rr = idx & 31;
        g_a[(size_t)c*RTOT + r0 + rr] = a_s[c*33 + rr];
        g_b[(size_t)c*RTOT + r0 + rr] = b_s[c*33 + rr];
    }
}

// ---------------------------------------------------------------- per-channel NT SGEMM
// out_c[i][j] = sum_k A_c[i][k]*B_c[j][k]; 128x128 block tile, k-chunk 32,
// 256 threads, 8x8 register tile.
__global__ void k_einsum()
{
    __shared__ float As[32*132];
    __shared__ float Bs[32*132];
    int c = blockIdx.z;
    const float* A = g_a + (size_t)c * RTOT;
    const float* B = g_b + (size_t)c * RTOT;
    float*       O = g_o + (size_t)c * RTOT;
    int i0 = blockIdx.y * 128, j0 = blockIdx.x * 128;
    int tid = threadIdx.x;
    int tr = tid >> 4, tc = tid & 15;
    int row0 = tr * 8, col0 = tc * 8;

    float acc[8][8];
    #pragma unroll
    for (int i = 0; i < 8; i++)
        #pragma unroll
        for (int j = 0; j < 8; j++) acc[i][j] = 0.f;

    for (int k0 = 0; k0 < NTOK; k0 += 32) {
        __syncthreads();
        #pragma unroll
        for (int l = 0; l < 4; l++) {
            int f = tid + l*256;          // 0..1023 float4s
            int rr = f >> 3, kq = f & 7;
            float4 va = *(const float4*)(A + (size_t)(i0+rr)*NTOK + k0 + kq*4);
            As[(kq*4+0)*132 + rr] = va.x;
            As[(kq*4+1)*132 + rr] = va.y;
            As[(kq*4+2)*132 + rr] = va.z;
            As[(kq*4+3)*132 + rr] = va.w;
            float4 vb = *(const float4*)(B + (size_t)(j0+rr)*NTOK + k0 + kq*4);
            Bs[(kq*4+0)*132 + rr] = vb.x;
            Bs[(kq*4+1)*132 + rr] = vb.y;
            Bs[(kq*4+2)*132 + rr] = vb.z;
            Bs[(kq*4+3)*132 + rr] = vb.w;
        }
        __syncthreads();
        #pragma unroll
        for (int kk = 0; kk < 32; kk++) {
            float af[8], bf[8];
            *(float4*)(af)   = *(const float4*)(&As[kk*132 + row0]);
            *(float4*)(af+4) = *(const float4*)(&As[kk*132 + row0 + 4]);
            *(float4*)(bf)   = *(const float4*)(&Bs[kk*132 + col0]);
            *(float4*)(bf+4) = *(const float4*)(&Bs[kk*132 + col0 + 4]);
            #pragma unroll
            for (int i = 0; i < 8; i++)
                #pragma unroll
                for (int j = 0; j < 8; j++)
                    acc[i][j] += af[i] * bf[j];
        }
    }

    #pragma unroll
    for (int ri = 0; ri < 8; ri++) {
        float* dst = O + (size_t)(i0 + row0 + ri)*NTOK + j0 + col0;
        float4 v0, v1;
        v0.x = acc[ri][0]; v0.y = acc[ri][1]; v0.z = acc[ri][2]; v0.w = acc[ri][3];
        v1.x = acc[ri][4]; v1.y = acc[ri][5]; v1.z = acc[ri][6]; v1.w = acc[ri][7];
        *(float4*)dst = v0;
        *(float4*)(dst + 4) = v1;
    }
}

// ---------------------------------------------------------------- LN2 + transpose
// block handles 32 consecutive r=(i,j); reads g_o[c][r] tiles, LN over c,
// writes g_u (=g_a) row-major [r][c].
__global__ void k_ln2t(const float* __restrict__ w, const float* __restrict__ b)
{
    __shared__ float t[128*33];
    __shared__ float red[8][33];
    __shared__ float mu_s[32], rstd_s[32];
    int tid = threadIdx.x;
    size_t r0 = (size_t)blockIdx.x * 32;

    for (int idx = tid; idx < CH*32; idx += 256) {
        int c = idx >> 5, rr = idx & 31;
        t[c*33 + rr] = g_o[(size_t)c*RTOT + r0 + rr];
    }
    __syncthreads();
    int rr = tid & 31, part = tid >> 5;
    float s = 0.f;
    for (int c = part*16; c < part*16 + 16; c++) s += t[c*33 + rr];
    red[part][rr] = s;
    __syncthreads();
    if (tid < 32) {
        float tot = 0.f;
        #pragma unroll
        for (int p = 0; p < 8; p++) tot += red[p][tid];
        mu_s[tid] = tot * (1.f/128.f);
    }
    __syncthreads();
    float mu = mu_s[rr], q = 0.f;
    for (int c = part*16; c < part*16 + 16; c++) {
        float d = t[c*33 + rr] - mu; q += d*d;
    }
    __syncthreads();
    red[part][rr] = q;
    __syncthreads();
    if (tid < 32) {
        float tot = 0.f;
        #pragma unroll
        for (int p = 0; p < 8; p++) tot += red[p][tid];
        rstd_s[tid] = rsqrtf(tot * (1.f/128.f) + 1e-5f);
    }
    __syncthreads();
    float* u = g_a;   // g_a is dead: reuse as u buffer
    for (int idx = tid; idx < CH*32; idx += 256) {
        int rr2 = idx >> 7, c = idx & 127;
        float val = (t[c*33 + rr2] - mu_s[rr2]) * rstd_s[rr2] * w[c] + b[c];
        u[(r0 + rr2)*CH + c] = val;
    }
}

// ---------------------------------------------------------------- final fused GEMM
// block: 64 rows x 256 cols (col j = 2c+q: q0 -> out_w row c applied to u,
// q1 -> gating_w row c applied to x). 256 threads, thread tile 8x8.
// out[r][c] = dot(u,out_w[c]) * sig(dot(x,gating_w[c]))
__global__ void k_final(const float* __restrict__ outw,
                        const float* __restrict__ gatingw,
                        float* __restrict__ out)
{
    __shared__ float Us[16*68];
    __shared__ float Xs[16*68];
    __shared__ float Ws[16*260];
    int tid = threadIdx.x;
    size_t r0 = (size_t)blockIdx.x * 64;
    int rg = tid >> 5;            // 0..7
    int jg = tid & 31;            // 0..31
    int r0l = rg * 8, j0 = jg * 8;

    const float* U = g_a + r0 * CH;
    const float* X = g_x + r0 * CH;

    float acc[8][8];
    #pragma unroll
    for (int i = 0; i < 8; i++)
        #pragma unroll
        for (int j = 0; j < 8; j++) acc[i][j] = 0.f;

    for (int k0 = 0; k0 < CH; k0 += 16) {
        __syncthreads();
        {   // U and X tiles: 64 rows x 16 = 256 float4 each
            int rr = tid >> 2, kq = tid & 3;
            float4 vu = *(const float4*)(U + (size_t)rr*CH + k0 + kq*4);
            Us[(kq*4+0)*68 + rr] = vu.x;
            Us[(kq*4+1)*68 + rr] = vu.y;
            Us[(kq*4+2)*68 + rr] = vu.z;
            Us[(kq*4+3)*68 + rr] = vu.w;
            float4 vx = *(const float4*)(X + (size_t)rr*CH + k0 + kq*4);
            Xs[(kq*4+0)*68 + rr] = vx.x;
            Xs[(kq*4+1)*68 + rr] = vx.y;
            Xs[(kq*4+2)*68 + rr] = vx.z;
            Xs[(kq*4+3)*68 + rr] = vx.w;
        }
        #pragma unroll
        for (int l = 0; l < 4; l++) {     // W tile: 256 x 16 = 1024 float4
            int f = tid + l*256;
            int j = f >> 2, kq = f & 3;
            int c = j >> 1, q = j & 1;
            const float* wsrc = q ? (gatingw + (size_t)c*CH) : (outw + (size_t)c*CH);
            float4 v = *(const float4*)(wsrc + k0 + kq*4);
            Ws[(kq*4+0)*260 + j] = v.x;
            Ws[(kq*4+1)*260 + j] = v.y;
            Ws[(kq*4+2)*260 + j] = v.z;
            Ws[(kq*4+3)*260 + j] = v.w;
        }
        __syncthreads();
        #pragma unroll
        for (int kk = 0; kk < 16; kk++) {
            float uf[8], xf[8];
            *(float4*)(uf)   = *(const float4*)(&Us[kk*68 + r0l]);
            *(float4*)(uf+4) = *(const float4*)(&Us[kk*68 + r0l + 4]);
            *(float4*)(xf)   = *(const float4*)(&Xs[kk*68 + r0l]);
            *(float4*)(xf+4) = *(const float4*)(&Xs[kk*68 + r0l + 4]);
            #pragma unroll
            for (int jj = 0; jj < 8; jj++) {
                float wv = Ws[kk*260 + j0 + jj];
                if (jj & 1) {
                    #pragma unroll
                    for (int i = 0; i < 8; i++) acc[i][jj] += xf[i] * wv;
                } else {
                    #pragma unroll
                    for (int i = 0; i < 8; i++) acc[i][jj] += uf[i] * wv;
                }
            }
        }
    }

    int co0 = j0 >> 1;   // 4 consecutive output channels
    #pragma unroll
    for (int ri = 0; ri < 8; ri++) {
        size_t r = r0 + r0l + ri;
        float4 o;
        o.x = acc[ri][0] * sigm(acc[ri][1]);
        o.y = acc[ri][2] * sigm(acc[ri][3]);
        o.z = acc[ri][4] * sigm(acc[ri][5]);
        o.w = acc[ri][6] * sigm(acc[ri][7]);
        *(float4*)(out + r*CH + co0) = o;
    }
}

// ---------------------------------------------------------------- launch
extern "C" void kernel_launch(void* const* d_in, const int* in_sizes, int n_in,
                              void* d_out, int out_size)
{
    const float* pair     = (const float*)d_in[0];
    const float* mask     = (const float*)d_in[1];
    const float* ln1_w    = (const float*)d_in[2];
    const float* ln1_b    = (const float*)d_in[3];
    const float* proj_w   = (const float*)d_in[4];
    const float* gate_w   = (const float*)d_in[5];
    const float* ln2_w    = (const float*)d_in[6];
    const float* ln2_b    = (const float*)d_in[7];
    const float* out_w    = (const float*)d_in[8];
    const float* gating_w = (const float*)d_in[9];
    float* out = (float*)d_out;

    k_ln1<<<RTOT/8, 256>>>(pair, ln1_w, ln1_b);
    k_projgate<<<RTOT/32, 256>>>(proj_w, gate_w, mask);
    k_einsum<<<dim3(NTOK/128, NTOK/128, CH), 256>>>();
    k_ln2t<<<RTOT/32, 256>>>(ln2_w, ln2_b);
    k_final<<<RTOT/64, 256>>>(out_w, gating_w, out);
}

// round 4
// speedup vs baseline: 1.3672x; 1.3664x over previous
#include <cuda_runtime.h>
#include <math.h>
#include <stdint.h>

// TriangleMultiplication: N=768, C=128
//   k_ln1       : x = LN(pair)                          -> g_x [r][c]
//   k_projgate  : a,b = split((x@Wp^T)*mask*sig(x@Wg^T)) -> g_a,g_b [c][i][k], tf32-rounded
//   k_einsum_mma: out_c = A_c @ B_c^T per channel (mma.sync tf32) -> g_o [c][i][j]
//   k_ln2t      : u = LN_c(out) transposed              -> g_u (=g_a reuse) [r][c]
//   k_final     : out = (u@Wo^T) * sig(x@Wgat^T)        -> d_out [r][c]

#define NTOK 768
#define CH   128
#define RTOT (NTOK*NTOK)   // 589824

__device__ float g_x[(size_t)RTOT*CH];
__device__ float g_a[(size_t)CH*RTOT];
__device__ float g_b[(size_t)CH*RTOT];
__device__ float g_o[(size_t)CH*RTOT];

__device__ __forceinline__ float sigm(float v){ return 1.f/(1.f+expf(-v)); }

__device__ __forceinline__ float tf32r(float x){
    uint32_t u;
    asm("cvt.rna.tf32.f32 %0, %1;" : "=r"(u) : "f"(x));
    return __uint_as_float(u);
}

// m16n8k8 tf32 warp MMA (sm_80+ baseline feature; works on compute_103)
__device__ __forceinline__ void mma8(float* d, const uint32_t* a, const uint32_t* b){
    asm volatile(
        "mma.sync.aligned.m16n8k8.row.col.f32.tf32.tf32.f32 "
        "{%0,%1,%2,%3}, {%4,%5,%6,%7}, {%8,%9}, {%0,%1,%2,%3};"
        : "+f"(d[0]), "+f"(d[1]), "+f"(d[2]), "+f"(d[3])
        : "r"(a[0]), "r"(a[1]), "r"(a[2]), "r"(a[3]), "r"(b[0]), "r"(b[1]));
}

// ---------------------------------------------------------------- LN1
__global__ void k_ln1(const float* __restrict__ pair,
                      const float* __restrict__ w,
                      const float* __restrict__ b)
{
    int warp = threadIdx.x >> 5, lane = threadIdx.x & 31;
    size_t r = (size_t)blockIdx.x * 8 + warp;
    const float4* src = (const float4*)(pair + r * CH);
    float4 v = src[lane];
    float s = v.x + v.y + v.z + v.w;
    #pragma unroll
    for (int o = 16; o; o >>= 1) s += __shfl_xor_sync(0xffffffffu, s, o);
    float mu = s * (1.f/128.f);
    float dx = v.x-mu, dy = v.y-mu, dz = v.z-mu, dw = v.w-mu;
    float q = dx*dx + dy*dy + dz*dz + dw*dw;
    #pragma unroll
    for (int o = 16; o; o >>= 1) q += __shfl_xor_sync(0xffffffffu, q, o);
    float rstd = rsqrtf(q * (1.f/128.f) + 1e-5f);
    float4 wv = ((const float4*)w)[lane];
    float4 bv = ((const float4*)b)[lane];
    float4 o4;
    o4.x = dx*rstd*wv.x + bv.x;
    o4.y = dy*rstd*wv.y + bv.y;
    o4.z = dz*rstd*wv.z + bv.z;
    o4.w = dw*rstd*wv.w + bv.w;
    ((float4*)(g_x + r * CH))[lane] = o4;
}

// ---------------------------------------------------------------- proj+gate
__global__ void k_projgate(const float* __restrict__ projw,
                           const float* __restrict__ gatew,
                           const float* __restrict__ mask)
{
    __shared__ float sm[16*36 + 16*520];
    float* Xs = sm;
    float* Ws = sm + 16*36;

    int tid = threadIdx.x;
    size_t r0 = (size_t)blockIdx.x * 32;
    int rg = tid >> 6;
    int jg = tid & 63;
    int r0l = rg * 8, j0 = jg * 8;

    float acc[8][8];
    #pragma unroll
    for (int i = 0; i < 8; i++)
        #pragma unroll
        for (int j = 0; j < 8; j++) acc[i][j] = 0.f;

    const float* X = g_x + r0 * CH;

    for (int k0 = 0; k0 < CH; k0 += 16) {
        __syncthreads();
        if (tid < 128) {
            int rr = tid >> 2, kq = tid & 3;
            float4 v = *(const float4*)(X + (size_t)rr*CH + k0 + kq*4);
            Xs[(kq*4+0)*36 + rr] = v.x;
            Xs[(kq*4+1)*36 + rr] = v.y;
            Xs[(kq*4+2)*36 + rr] = v.z;
            Xs[(kq*4+3)*36 + rr] = v.w;
        }
        #pragma unroll
        for (int l = 0; l < 8; l++) {
            int f = tid + l*256;
            int j = f >> 2, kq = f & 3;
            int c = j >> 2, q = j & 3;
            const float* wsrc = (q < 2) ? (projw + (size_t)(2*c+q)*CH)
                                        : (gatew + (size_t)(2*c+q-2)*CH);
            float4 v = *(const float4*)(wsrc + k0 + kq*4);
            Ws[(kq*4+0)*520 + j] = v.x;
            Ws[(kq*4+1)*520 + j] = v.y;
            Ws[(kq*4+2)*520 + j] = v.z;
            Ws[(kq*4+3)*520 + j] = v.w;
        }
        __syncthreads();
        #pragma unroll
        for (int kk = 0; kk < 16; kk++) {
            float xf[8], wf[8];
            *(float4*)(xf)   = *(const float4*)(&Xs[kk*36 + r0l]);
            *(float4*)(xf+4) = *(const float4*)(&Xs[kk*36 + r0l + 4]);
            *(float4*)(wf)   = *(const float4*)(&Ws[kk*520 + j0]);
            *(float4*)(wf+4) = *(const float4*)(&Ws[kk*520 + j0 + 4]);
            #pragma unroll
            for (int i = 0; i < 8; i++)
                #pragma unroll
                for (int j = 0; j < 8; j++)
                    acc[i][j] += xf[i] * wf[j];
        }
    }

    __syncthreads();
    float* a_s = sm;
    float* b_s = sm + 4224;
    int c0 = j0 >> 2;
    #pragma unroll
    for (int ri = 0; ri < 8; ri++) {
        int rl = r0l + ri;
        float mk = mask[(int)((r0 + rl) % NTOK)];
        #pragma unroll
        for (int h = 0; h < 2; h++) {
            int c = c0 + h;
            float p0 = acc[ri][h*4+0], p1 = acc[ri][h*4+1];
            float g0 = acc[ri][h*4+2], g1 = acc[ri][h*4+3];
            a_s[c*33 + rl] = tf32r(p0 * mk * sigm(g0));
            b_s[c*33 + rl] = tf32r(p1 * mk * sigm(g1));
        }
    }
    __syncthreads();
    for (int idx = tid; idx < CH*32; idx += 256) {
        int c = idx >> 5, rr = idx & 31;
        g_a[(size_t)c*RTOT + r0 + rr] = a_s[c*33 + rr];
        g_b[(size_t)c*RTOT + r0 + rr] = b_s[c*33 + rr];
    }
}

// ---------------------------------------------------------------- tf32 mma.sync einsum
// per channel: C = A(128x768) @ B(128x768)^T. CTA tile 128x128, 8 warps (2x4),
// warp tile 64x32 via m16n8k8.  Smem row-major [i][k], stride 36 (conflict-free
// fragment loads; STS.128 at the 4-phase floor).  Double-buffered K-chunks of 32.
#define KC 32
#define NCHUNK (NTOK/KC)           // 24
#define ESTRIDE 36
#define EBUF (128*ESTRIDE)         // floats per matrix per buffer
#define DSMEM (4*EBUF*4)           // 2 bufs x (A,B) x 128*36 floats = 73728 B

__global__ void __launch_bounds__(256, 2) k_einsum_mma()
{
    extern __shared__ float sm[];
    int c  = blockIdx.z;
    int i0 = blockIdx.y * 128;
    int j0 = blockIdx.x * 128;
    const float* A = g_a + (size_t)c*RTOT + (size_t)i0*NTOK;
    const float* B = g_b + (size_t)c*RTOT + (size_t)j0*NTOK;
    float*       O = g_o + (size_t)c*RTOT;

    int tid = threadIdx.x, lane = tid & 31, warp = tid >> 5;
    int wm = (warp >> 2) * 64;     // warp M offset (0/64)
    int wn = (warp & 3) * 32;      // warp N offset (0/32/64/96)

    float acc[4][4][4];
    #pragma unroll
    for (int mt = 0; mt < 4; mt++)
        #pragma unroll
        for (int nt = 0; nt < 4; nt++)
            #pragma unroll
            for (int e = 0; e < 4; e++) acc[mt][nt][e] = 0.f;

    int rr = tid >> 3, q = tid & 7;      // loader mapping: 32 rows x 8 float4

    // prologue: chunk 0 -> buffer 0
    {
        float* dA = sm;
        float* dB = sm + EBUF;
        #pragma unroll
        for (int l = 0; l < 4; l++) {
            int r = rr + l*32;
            *(float4*)(dA + r*ESTRIDE + q*4) = *(const float4*)(A + (size_t)r*NTOK + q*4);
            *(float4*)(dB + r*ESTRIDE + q*4) = *(const float4*)(B + (size_t)r*NTOK + q*4);
        }
    }
    __syncthreads();

    int arow = lane >> 2, acol = lane & 3;

    for (int kc = 0; kc < NCHUNK; kc++) {
        int buf = kc & 1;
        if (kc + 1 < NCHUNK) {
            float* dA = sm + (buf^1)*2*EBUF;
            float* dB = dA + EBUF;
            const float* As = A + (kc+1)*KC;
            const float* Bsrc = B + (kc+1)*KC;
            #pragma unroll
            for (int l = 0; l < 4; l++) {
                int r = rr + l*32;
                *(float4*)(dA + r*ESTRIDE + q*4) = *(const float4*)(As + (size_t)r*NTOK + q*4);
                *(float4*)(dB + r*ESTRIDE + q*4) = *(const float4*)(Bsrc + (size_t)r*NTOK + q*4);
            }
        }
        const float* cA = sm + buf*2*EBUF;
        const float* cB = cA + EBUF;
        #pragma unroll
        for (int ks = 0; ks < 4; ks++) {
            int kb = ks * 8;
            uint32_t af[4][4], bf[4][2];
            #pragma unroll
            for (int mt = 0; mt < 4; mt++) {
                const float* base = cA + (wm + mt*16 + arow)*ESTRIDE + kb + acol;
                af[mt][0] = __float_as_uint(base[0]);
                af[mt][1] = __float_as_uint(base[8*ESTRIDE]);
                af[mt][2] = __float_as_uint(base[4]);
                af[mt][3] = __float_as_uint(base[8*ESTRIDE + 4]);
            }
            #pragma unroll
            for (int nt = 0; nt < 4; nt++) {
                const float* base = cB + (wn + nt*8 + arow)*ESTRIDE + kb + acol;
                bf[nt][0] = __float_as_uint(base[0]);
                bf[nt][1] = __float_as_uint(base[4]);
            }
            #pragma unroll
            for (int mt = 0; mt < 4; mt++)
                #pragma unroll
                for (int nt = 0; nt < 4; nt++)
                    mma8(acc[mt][nt], af[mt], bf[nt]);
        }
        __syncthreads();
    }

    // epilogue: write D fragments (float2 pairs, +8-row partner)
    int crow = lane >> 2, ccol = (lane & 3) * 2;
    #pragma unroll
    for (int mt = 0; mt < 4; mt++) {
        #pragma unroll
        for (int nt = 0; nt < 4; nt++) {
            float* d0 = O + (size_t)(i0 + wm + mt*16 + crow)*NTOK + j0 + wn + nt*8 + ccol;
            float2 v0; v0.x = acc[mt][nt][0]; v0.y = acc[mt][nt][1];
            float2 v1; v1.x = acc[mt][nt][2]; v1.y = acc[mt][nt][3];
            *(float2*)d0 = v0;
            *(float2*)(d0 + 8*NTOK) = v1;
        }
    }
}

// ---------------------------------------------------------------- LN2 + transpose
__global__ void k_ln2t(const float* __restrict__ w, const float* __restrict__ b)
{
    __shared__ float t[128*33];
    __shared__ float red[8][33];
    __shared__ float mu_s[32], rstd_s[32];
    int tid = threadIdx.x;
    size_t r0 = (size_t)blockIdx.x * 32;

    for (int idx = tid; idx < CH*32; idx += 256) {
        int c = idx >> 5, rr = idx & 31;
        t[c*33 + rr] = g_o[(size_t)c*RTOT + r0 + rr];
    }
    __syncthreads();
    int rr = tid & 31, part = tid >> 5;
    float s = 0.f;
    for (int c = part*16; c < part*16 + 16; c++) s += t[c*33 + rr];
    red[part][rr] = s;
    __syncthreads();
    if (tid < 32) {
        float tot = 0.f;
        #pragma unroll
        for (int p = 0; p < 8; p++) tot += red[p][tid];
        mu_s[tid] = tot * (1.f/128.f);
    }
    __syncthreads();
    float mu = mu_s[rr], qv = 0.f;
    for (int c = part*16; c < part*16 + 16; c++) {
        float d = t[c*33 + rr] - mu; qv += d*d;
    }
    __syncthreads();
    red[part][rr] = qv;
    __syncthreads();
    if (tid < 32) {
        float tot = 0.f;
        #pragma unroll
        for (int p = 0; p < 8; p++) tot += red[p][tid];
        rstd_s[tid] = rsqrtf(tot * (1.f/128.f) + 1e-5f);
    }
    __syncthreads();
    float* u = g_a;   // g_a is dead: reuse as u buffer
    for (int idx = tid; idx < CH*32; idx += 256) {
        int rr2 = idx >> 7, c = idx & 127;
        float val = (t[c*33 + rr2] - mu_s[rr2]) * rstd_s[rr2] * w[c] + b[c];
        u[(r0 + rr2)*CH + c] = val;
    }
}

// ---------------------------------------------------------------- final fused GEMM
__global__ void k_final(const float* __restrict__ outw,
                        const float* __restrict__ gatingw,
                        float* __restrict__ out)
{
    __shared__ float Us[16*68];
    __shared__ float Xs[16*68];
    __shared__ float Ws[16*260];
    int tid = threadIdx.x;
    size_t r0 = (size_t)blockIdx.x * 64;
    int rg = tid >> 5;
    int jg = tid & 31;
    int r0l = rg * 8, j0 = jg * 8;

    const float* U = g_a + r0 * CH;
    const float* X = g_x + r0 * CH;

    float acc[8][8];
    #pragma unroll
    for (int i = 0; i < 8; i++)
        #pragma unroll
        for (int j = 0; j < 8; j++) acc[i][j] = 0.f;

    for (int k0 = 0; k0 < CH; k0 += 16) {
        __syncthreads();
        {
            int rr = tid >> 2, kq = tid & 3;
            float4 vu = *(const float4*)(U + (size_t)rr*CH + k0 + kq*4);
            Us[(kq*4+0)*68 + rr] = vu.x;
            Us[(kq*4+1)*68 + rr] = vu.y;
            Us[(kq*4+2)*68 + rr] = vu.z;
            Us[(kq*4+3)*68 + rr] = vu.w;
            float4 vx = *(const float4*)(X + (size_t)rr*CH + k0 + kq*4);
            Xs[(kq*4+0)*68 + rr] = vx.x;
            Xs[(kq*4+1)*68 + rr] = vx.y;
            Xs[(kq*4+2)*68 + rr] = vx.z;
            Xs[(kq*4+3)*68 + rr] = vx.w;
        }
        #pragma unroll
        for (int l = 0; l < 4; l++) {
            int f = tid + l*256;
            int j = f >> 2, kq = f & 3;
            int c = j >> 1, q2 = j & 1;
            const float* wsrc = q2 ? (gatingw + (size_t)c*CH) : (outw + (size_t)c*CH);
            float4 v = *(const float4*)(wsrc + k0 + kq*4);
            Ws[(kq*4+0)*260 + j] = v.x;
            Ws[(kq*4+1)*260 + j] = v.y;
            Ws[(kq*4+2)*260 + j] = v.z;
            Ws[(kq*4+3)*260 + j] = v.w;
        }
        __syncthreads();
        #pragma unroll
        for (int kk = 0; kk < 16; kk++) {
            float uf[8], xf[8];
            *(float4*)(uf)   = *(const float4*)(&Us[kk*68 + r0l]);
            *(float4*)(uf+4) = *(const float4*)(&Us[kk*68 + r0l + 4]);
            *(float4*)(xf)   = *(const float4*)(&Xs[kk*68 + r0l]);
            *(float4*)(xf+4) = *(const float4*)(&Xs[kk*68 + r0l + 4]);
            #pragma unroll
            for (int jj = 0; jj < 8; jj++) {
                float wv = Ws[kk*260 + j0 + jj];
                if (jj & 1) {
                    #pragma unroll
                    for (int i = 0; i < 8; i++) acc[i][jj] += xf[i] * wv;
                } else {
                    #pragma unroll
                    for (int i = 0; i < 8; i++) acc[i][jj] += uf[i] * wv;
                }
            }
        }
    }

    int co0 = j0 >> 1;
    #pragma unroll
    for (int ri = 0; ri < 8; ri++) {
        size_t r = r0 + r0l + ri;
        float4 o;
        o.x = acc[ri][0] * sigm(acc[ri][1]);
        o.y = acc[ri][2] * sigm(acc[ri][3]);
        o.z = acc[ri][4] * sigm(acc[ri][5]);
        o.w = acc[ri][6] * sigm(acc[ri][7]);
        *(float4*)(out + r*CH + co0) = o;
    }
}

// ---------------------------------------------------------------- launch
extern "C" void kernel_launch(void* const* d_in, const int* in_sizes, int n_in,
                              void* d_out, int out_size)
{
    const float* pair     = (const float*)d_in[0];
    const float* mask     = (const float*)d_in[1];
    const float* ln1_w    = (const float*)d_in[2];
    const float* ln1_b    = (const float*)d_in[3];
    const float* proj_w   = (const float*)d_in[4];
    const float* gate_w   = (const float*)d_in[5];
    const float* ln2_w    = (const float*)d_in[6];
    const float* ln2_b    = (const float*)d_in[7];
    const float* out_w    = (const float*)d_in[8];
    const float* gating_w = (const float*)d_in[9];
    float* out = (float*)d_out;

    cudaFuncSetAttribute(k_einsum_mma, cudaFuncAttributeMaxDynamicSharedMemorySize, DSMEM);

    k_ln1<<<RTOT/8, 256>>>(pair, ln1_w, ln1_b);
    k_projgate<<<RTOT/32, 256>>>(proj_w, gate_w, mask);
    k_einsum_mma<<<dim3(NTOK/128, NTOK/128, CH), 256, DSMEM>>>();
    k_ln2t<<<RTOT/32, 256>>>(ln2_w, ln2_b);
    k_final<<<RTOT/64, 256>>>(out_w, gating_w, out);
}

// round 5
// speedup vs baseline: 1.8485x; 1.3521x over previous
#include <cuda_runtime.h>
#include <math.h>
#include <stdint.h>

// TriangleMultiplication: N=768, C=128
//   k_ln1          : x = LN(pair)                         -> g_x [r][c]
//   k_projgate_mma : a,b = split((x@Wp^T)*mask*sig(x@Wg^T)) -> g_a,g_b [c][r], tf32 mma
//   k_einsum_mma   : out_c = A_c @ B_c^T per channel (tf32 mma) -> g_o [c][i][j]
//   k_ln2t         : u = LN_c(out) transposed             -> g_u (=g_a reuse) [r][c]
//   k_final_mma    : out = (u@Wo^T) * sig(x@Wgat^T) (2 fused tf32 GEMMs) -> d_out

#define NTOK 768
#define CH   128
#define RTOT (NTOK*NTOK)   // 589824

__device__ float g_x[(size_t)RTOT*CH];
__device__ float g_a[(size_t)CH*RTOT];
__device__ float g_b[(size_t)CH*RTOT];
__device__ float g_o[(size_t)CH*RTOT];

__device__ __forceinline__ float sigm(float v){ return 1.f/(1.f+expf(-v)); }

__device__ __forceinline__ float tf32r(float x){
    uint32_t u;
    asm("cvt.rna.tf32.f32 %0, %1;" : "=r"(u) : "f"(x));
    return __uint_as_float(u);
}
__device__ __forceinline__ float4 tf32r4(float4 v){
    v.x = tf32r(v.x); v.y = tf32r(v.y); v.z = tf32r(v.z); v.w = tf32r(v.w);
    return v;
}

// m16n8k8 tf32 warp MMA (sm_80+ baseline feature)
__device__ __forceinline__ void mma8(float* d, const uint32_t* a, const uint32_t* b){
    asm volatile(
        "mma.sync.aligned.m16n8k8.row.col.f32.tf32.tf32.f32 "
        "{%0,%1,%2,%3}, {%4,%5,%6,%7}, {%8,%9}, {%0,%1,%2,%3};"
        : "+f"(d[0]), "+f"(d[1]), "+f"(d[2]), "+f"(d[3])
        : "r"(a[0]), "r"(a[1]), "r"(a[2]), "r"(a[3]), "r"(b[0]), "r"(b[1]));
}

#define ESTRIDE 36
#define TBUF (128*ESTRIDE)         // floats per 128x32 tile (stride 36)

// ---------------------------------------------------------------- LN1
__global__ void k_ln1(const float* __restrict__ pair,
                      const float* __restrict__ w,
                      const float* __restrict__ b)
{
    int warp = threadIdx.x >> 5, lane = threadIdx.x & 31;
    size_t r = (size_t)blockIdx.x * 8 + warp;
    const float4* src = (const float4*)(pair + r * CH);
    float4 v = src[lane];
    float s = v.x + v.y + v.z + v.w;
    #pragma unroll
    for (int o = 16; o; o >>= 1) s += __shfl_xor_sync(0xffffffffu, s, o);
    float mu = s * (1.f/128.f);
    float dx = v.x-mu, dy = v.y-mu, dz = v.z-mu, dw = v.w-mu;
    float q = dx*dx + dy*dy + dz*dz + dw*dw;
    #pragma unroll
    for (int o = 16; o; o >>= 1) q += __shfl_xor_sync(0xffffffffu, q, o);
    float rstd = rsqrtf(q * (1.f/128.f) + 1e-5f);
    float4 wv = ((const float4*)w)[lane];
    float4 bv = ((const float4*)b)[lane];
    float4 o4;
    o4.x = dx*rstd*wv.x + bv.x;
    o4.y = dy*rstd*wv.y + bv.y;
    o4.z = dz*rstd*wv.z + bv.z;
    o4.w = dw*rstd*wv.w + bv.w;
    ((float4*)(g_x + r * CH))[lane] = o4;
}

// ---------------------------------------------------------------- proj+gate (tf32 mma)
// CTA: 128 rows x 128 virtual cols (jv = 4c+q : p0,p1,g0,g1 for channel c).
// grid (4, RTOT/128): blockIdx.x = channel-group (fast -> L2 reuse of X tile).
// Double-buffered K-chunks of 32 (K=128 total).
#define PG_SMEM (4*TBUF*4)   // 2 bufs x (X,W) = 73728 B

__global__ void __launch_bounds__(256, 2) k_projgate_mma(
    const float* __restrict__ projw,
    const float* __restrict__ gatew,
    const float* __restrict__ mask)
{
    extern __shared__ float sm[];
    __shared__ float m_s[128];
    int tid = threadIdx.x, lane = tid & 31, warp = tid >> 5;
    int cg = blockIdx.x;                       // 0..3
    size_t i0 = (size_t)blockIdx.y * 128;
    const float* A = g_x + i0 * CH;

    if (tid < 128) m_s[tid] = mask[(int)(i0 % NTOK) + tid];

    int wm = (warp >> 2) * 64;
    int wn = (warp & 3) * 32;

    float acc[4][4][4];
    #pragma unroll
    for (int mt = 0; mt < 4; mt++)
        #pragma unroll
        for (int nt = 0; nt < 4; nt++)
            #pragma unroll
            for (int e = 0; e < 4; e++) acc[mt][nt][e] = 0.f;

    int rr = tid >> 3, q8 = tid & 7;
    const float* wp[4];
    #pragma unroll
    for (int l = 0; l < 4; l++) {
        int jv = cg*128 + rr + l*32;
        int c = jv >> 2, q = jv & 3;
        wp[l] = (q < 2) ? (projw + (size_t)(2*c+q)*CH)
                        : (gatew + (size_t)(2*c+q-2)*CH);
    }

    // prologue: chunk 0 -> buffer 0
    {
        float* dX = sm;
        float* dW = sm + TBUF;
        #pragma unroll
        for (int l = 0; l < 4; l++) {
            int r = rr + l*32;
            *(float4*)(dX + r*ESTRIDE + q8*4) = tf32r4(*(const float4*)(A + (size_t)r*CH + q8*4));
            *(float4*)(dW + r*ESTRIDE + q8*4) = tf32r4(*(const float4*)(wp[l] + q8*4));
        }
    }
    __syncthreads();

    int arow = lane >> 2, acol = lane & 3;

    #pragma unroll
    for (int kc = 0; kc < 4; kc++) {
        int buf = kc & 1;
        if (kc + 1 < 4) {
            float* dX = sm + (buf^1)*2*TBUF;
            float* dW = dX + TBUF;
            int k0 = (kc+1)*32;
            #pragma unroll
            for (int l = 0; l < 4; l++) {
                int r = rr + l*32;
                *(float4*)(dX + r*ESTRIDE + q8*4) = tf32r4(*(const float4*)(A + (size_t)r*CH + k0 + q8*4));
                *(float4*)(dW + r*ESTRIDE + q8*4) = tf32r4(*(const float4*)(wp[l] + k0 + q8*4));
            }
        }
        const float* cX = sm + buf*2*TBUF;
        const float* cW = cX + TBUF;
        #pragma unroll
        for (int ks = 0; ks < 4; ks++) {
            int kb = ks * 8;
            uint32_t af[4][4], bf[4][2];
            #pragma unroll
            for (int mt = 0; mt < 4; mt++) {
                const float* base = cX + (wm + mt*16 + arow)*ESTRIDE + kb + acol;
                af[mt][0] = __float_as_uint(base[0]);
                af[mt][1] = __float_as_uint(base[8*ESTRIDE]);
                af[mt][2] = __float_as_uint(base[4]);
                af[mt][3] = __float_as_uint(base[8*ESTRIDE + 4]);
            }
            #pragma unroll
            for (int nt = 0; nt < 4; nt++) {
                const float* base = cW + (wn + nt*8 + arow)*ESTRIDE + kb + acol;
                bf[nt][0] = __float_as_uint(base[0]);
                bf[nt][1] = __float_as_uint(base[4]);
            }
            #pragma unroll
            for (int mt = 0; mt < 4; mt++)
                #pragma unroll
                for (int nt = 0; nt < 4; nt++)
                    mma8(acc[mt][nt], af[mt], bf[nt]);
        }
        __syncthreads();
    }

    // epilogue: even lanes hold (p0,p1), odd lanes hold (g0,g1) for same channel/rows.
    float* a_s = sm;              // [32][132]
    float* b_s = sm + 32*132;
    int crow = lane >> 2, ccol = (lane & 3) * 2;
    #pragma unroll
    for (int mt = 0; mt < 4; mt++) {
        #pragma unroll
        for (int nt = 0; nt < 4; nt++) {
            float g0r1 = __shfl_xor_sync(0xffffffffu, acc[mt][nt][0], 1);
            float g1r1 = __shfl_xor_sync(0xffffffffu, acc[mt][nt][1], 1);
            float g0r2 = __shfl_xor_sync(0xffffffffu, acc[mt][nt][2], 1);
            float g1r2 = __shfl_xor_sync(0xffffffffu, acc[mt][nt][3], 1);
            if ((lane & 1) == 0) {
                int j  = wn + nt*8 + ccol;
                int cl = j >> 2;
                int r1 = wm + mt*16 + crow, r2 = r1 + 8;
                float mk1 = m_s[r1], mk2 = m_s[r2];
                a_s[cl*132 + r1] = tf32r(acc[mt][nt][0] * mk1 * sigm(g0r1));
                b_s[cl*132 + r1] = tf32r(acc[mt][nt][1] * mk1 * sigm(g1r1));
                a_s[cl*132 + r2] = tf32r(acc[mt][nt][2] * mk2 * sigm(g0r2));
                b_s[cl*132 + r2] = tf32r(acc[mt][nt][3] * mk2 * sigm(g1r2));
            }
        }
    }
    __syncthreads();
    int cb = cg * 32;
    #pragma unroll
    for (int it = 0; it < 4; it++) {
        int idx = tid + it*256;              // 0..1023
        int ch = idx >> 5, f4 = idx & 31;
        *(float4*)(g_a + (size_t)(cb+ch)*RTOT + i0 + f4*4) = *(float4*)(a_s + ch*132 + f4*4);
        *(float4*)(g_b + (size_t)(cb+ch)*RTOT + i0 + f4*4) = *(float4*)(b_s + ch*132 + f4*4);
    }
}

// ---------------------------------------------------------------- tf32 mma einsum
#define KC 32
#define NCHUNK (NTOK/KC)           // 24
#define EBUF TBUF
#define DSMEM (4*EBUF*4)           // 73728 B

__global__ void __launch_bounds__(256, 2) k_einsum_mma()
{
    extern __shared__ float sm[];
    int c  = blockIdx.z;
    int i0 = blockIdx.y * 128;
    int j0 = blockIdx.x * 128;
    const float* A = g_a + (size_t)c*RTOT + (size_t)i0*NTOK;
    const float* B = g_b + (size_t)c*RTOT + (size_t)j0*NTOK;
    float*       O = g_o + (size_t)c*RTOT;

    int tid = threadIdx.x, lane = tid & 31, warp = tid >> 5;
    int wm = (warp >> 2) * 64;
    int wn = (warp & 3) * 32;

    float acc[4][4][4];
    #pragma unroll
    for (int mt = 0; mt < 4; mt++)
        #pragma unroll
        for (int nt = 0; nt < 4; nt++)
            #pragma unroll
            for (int e = 0; e < 4; e++) acc[mt][nt][e] = 0.f;

    int rr = tid >> 3, q = tid & 7;

    {
        float* dA = sm;
        float* dB = sm + EBUF;
        #pragma unroll
        for (int l = 0; l < 4; l++) {
            int r = rr + l*32;
            *(float4*)(dA + r*ESTRIDE + q*4) = *(const float4*)(A + (size_t)r*NTOK + q*4);
            *(float4*)(dB + r*ESTRIDE + q*4) = *(const float4*)(B + (size_t)r*NTOK + q*4);
        }
    }
    __syncthreads();

    int arow = lane >> 2, acol = lane & 3;

    for (int kc = 0; kc < NCHUNK; kc++) {
        int buf = kc & 1;
        if (kc + 1 < NCHUNK) {
            float* dA = sm + (buf^1)*2*EBUF;
            float* dB = dA + EBUF;
            const float* As = A + (kc+1)*KC;
            const float* Bsrc = B + (kc+1)*KC;
            #pragma unroll
            for (int l = 0; l < 4; l++) {
                int r = rr + l*32;
                *(float4*)(dA + r*ESTRIDE + q*4) = *(const float4*)(As + (size_t)r*NTOK + q*4);
                *(float4*)(dB + r*ESTRIDE + q*4) = *(const float4*)(Bsrc + (size_t)r*NTOK + q*4);
            }
        }
        const float* cA = sm + buf*2*EBUF;
        const float* cB = cA + EBUF;
        #pragma unroll
        for (int ks = 0; ks < 4; ks++) {
            int kb = ks * 8;
            uint32_t af[4][4], bf[4][2];
            #pragma unroll
            for (int mt = 0; mt < 4; mt++) {
                const float* base = cA + (wm + mt*16 + arow)*ESTRIDE + kb + acol;
                af[mt][0] = __float_as_uint(base[0]);
                af[mt][1] = __float_as_uint(base[8*ESTRIDE]);
                af[mt][2] = __float_as_uint(base[4]);
                af[mt][3] = __float_as_uint(base[8*ESTRIDE + 4]);
            }
            #pragma unroll
            for (int nt = 0; nt < 4; nt++) {
                const float* base = cB + (wn + nt*8 + arow)*ESTRIDE + kb + acol;
                bf[nt][0] = __float_as_uint(base[0]);
                bf[nt][1] = __float_as_uint(base[4]);
            }
            #pragma unroll
            for (int mt = 0; mt < 4; mt++)
                #pragma unroll
                for (int nt = 0; nt < 4; nt++)
                    mma8(acc[mt][nt], af[mt], bf[nt]);
        }
        __syncthreads();
    }

    int crow = lane >> 2, ccol = (lane & 3) * 2;
    #pragma unroll
    for (int mt = 0; mt < 4; mt++) {
        #pragma unroll
        for (int nt = 0; nt < 4; nt++) {
            float* d0 = O + (size_t)(i0 + wm + mt*16 + crow)*NTOK + j0 + wn + nt*8 + ccol;
            float2 v0; v0.x = acc[mt][nt][0]; v0.y = acc[mt][nt][1];
            float2 v1; v1.x = acc[mt][nt][2]; v1.y = acc[mt][nt][3];
            *(float2*)d0 = v0;
            *(float2*)(d0 + 8*NTOK) = v1;
        }
    }
}

// ---------------------------------------------------------------- LN2 + transpose
__global__ void k_ln2t(const float* __restrict__ w, const float* __restrict__ b)
{
    __shared__ float t[128*33];
    __shared__ float red[8][33];
    __shared__ float mu_s[32], rstd_s[32];
    int tid = threadIdx.x;
    size_t r0 = (size_t)blockIdx.x * 32;

    for (int idx = tid; idx < CH*32; idx += 256) {
        int c = idx >> 5, rr = idx & 31;
        t[c*33 + rr] = g_o[(size_t)c*RTOT + r0 + rr];
    }
    __syncthreads();
    int rr = tid & 31, part = tid >> 5;
    float s = 0.f;
    for (int c = part*16; c < part*16 + 16; c++) s += t[c*33 + rr];
    red[part][rr] = s;
    __syncthreads();
    if (tid < 32) {
        float tot = 0.f;
        #pragma unroll
        for (int p = 0; p < 8; p++) tot += red[p][tid];
        mu_s[tid] = tot * (1.f/128.f);
    }
    __syncthreads();
    float mu = mu_s[rr], qv = 0.f;
    for (int c = part*16; c < part*16 + 16; c++) {
        float d = t[c*33 + rr] - mu; qv += d*d;
    }
    __syncthreads();
    red[part][rr] = qv;
    __syncthreads();
    if (tid < 32) {
        float tot = 0.f;
        #pragma unroll
        for (int p = 0; p < 8; p++) tot += red[p][tid];
        rstd_s[tid] = rsqrtf(tot * (1.f/128.f) + 1e-5f);
    }
    __syncthreads();
    float* u = g_a;   // g_a is dead: reuse as u buffer
    for (int idx = tid; idx < CH*32; idx += 256) {
        int rr2 = idx >> 7, c = idx & 127;
        float val = (t[c*33 + rr2] - mu_s[rr2]) * rstd_s[rr2] * w[c] + b[c];
        u[(r0 + rr2)*CH + c] = val;
    }
}

// ---------------------------------------------------------------- final (2 fused tf32 GEMMs)
// D1 = U @ OutW^T, D2 = X @ GatW^T (both 128x128 per CTA); out = D1 * sig(D2).
#define FN_SMEM (8*TBUF*4)   // 2 bufs x (U,X,Wo,Wg) = 147456 B

__global__ void __launch_bounds__(256, 1) k_final_mma(
    const float* __restrict__ outw,
    const float* __restrict__ gatingw,
    float* __restrict__ out)
{
    extern __shared__ float sm[];
    int tid = threadIdx.x, lane = tid & 31, warp = tid >> 5;
    size_t i0 = (size_t)blockIdx.x * 128;
    const float* U = g_a + i0 * CH;
    const float* X = g_x + i0 * CH;

    int wm = (warp >> 2) * 64;
    int wn = (warp & 3) * 32;

    float accU[4][4][4], accX[4][4][4];
    #pragma unroll
    for (int mt = 0; mt < 4; mt++)
        #pragma unroll
        for (int nt = 0; nt < 4; nt++)
            #pragma unroll
            for (int e = 0; e < 4; e++) { accU[mt][nt][e] = 0.f; accX[mt][nt][e] = 0.f; }

    int rr = tid >> 3, q8 = tid & 7;

    // buffer b at sm + b*4*TBUF; within: [U | X | Wo | Wg]
    {
        float* d0 = sm;
        #pragma unroll
        for (int l = 0; l < 4; l++) {
            int r = rr + l*32;
            *(float4*)(d0 + 0*TBUF + r*ESTRIDE + q8*4) = tf32r4(*(const float4*)(U + (size_t)r*CH + q8*4));
            *(float4*)(d0 + 1*TBUF + r*ESTRIDE + q8*4) = tf32r4(*(const float4*)(X + (size_t)r*CH + q8*4));
            *(float4*)(d0 + 2*TBUF + r*ESTRIDE + q8*4) = tf32r4(*(const float4*)(outw + (size_t)r*CH + q8*4));
            *(float4*)(d0 + 3*TBUF + r*ESTRIDE + q8*4) = tf32r4(*(const float4*)(gatingw + (size_t)r*CH + q8*4));
        }
    }
    __syncthreads();

    int arow = lane >> 2, acol = lane & 3;

    #pragma unroll
    for (int kc = 0; kc < 4; kc++) {
        int buf = kc & 1;
        if (kc + 1 < 4) {
            float* d0 = sm + (buf^1)*4*TBUF;
            int k0 = (kc+1)*32;
            #pragma unroll
            for (int l = 0; l < 4; l++) {
                int r = rr + l*32;
                *(float4*)(d0 + 0*TBUF + r*ESTRIDE + q8*4) = tf32r4(*(const float4*)(U + (size_t)r*CH + k0 + q8*4));
                *(float4*)(d0 + 1*TBUF + r*ESTRIDE + q8*4) = tf32r4(*(const float4*)(X + (size_t)r*CH + k0 + q8*4));
                *(float4*)(d0 + 2*TBUF + r*ESTRIDE + q8*4) = tf32r4(*(const float4*)(outw + (size_t)r*CH + k0 + q8*4));
                *(float4*)(d0 + 3*TBUF + r*ESTRIDE + q8*4) = tf32r4(*(const float4*)(gatingw + (size_t)r*CH + k0 + q8*4));
            }
        }
        const float* cb = sm + buf*4*TBUF;
        #pragma unroll
        for (int ks = 0; ks < 4; ks++) {
            int kb = ks * 8;
            uint32_t au[4][4], ax[4][4], bo[4][2], bg[4][2];
            #pragma unroll
            for (int mt = 0; mt < 4; mt++) {
                const float* bu = cb + 0*TBUF + (wm + mt*16 + arow)*ESTRIDE + kb + acol;
                au[mt][0] = __float_as_uint(bu[0]);
                au[mt][1] = __float_as_uint(bu[8*ESTRIDE]);
                au[mt][2] = __float_as_uint(bu[4]);
                au[mt][3] = __float_as_uint(bu[8*ESTRIDE + 4]);
                const float* bx = cb + 1*TBUF + (wm + mt*16 + arow)*ESTRIDE + kb + acol;
                ax[mt][0] = __float_as_uint(bx[0]);
                ax[mt][1] = __float_as_uint(bx[8*ESTRIDE]);
                ax[mt][2] = __float_as_uint(bx[4]);
                ax[mt][3] = __float_as_uint(bx[8*ESTRIDE + 4]);
            }
            #pragma unroll
            for (int nt = 0; nt < 4; nt++) {
                const float* po = cb + 2*TBUF + (wn + nt*8 + arow)*ESTRIDE + kb + acol;
                bo[nt][0] = __float_as_uint(po[0]);
                bo[nt][1] = __float_as_uint(po[4]);
                const float* pg = cb + 3*TBUF + (wn + nt*8 + arow)*ESTRIDE + kb + acol;
                bg[nt][0] = __float_as_uint(pg[0]);
                bg[nt][1] = __float_as_uint(pg[4]);
            }
            #pragma unroll
            for (int mt = 0; mt < 4; mt++)
                #pragma unroll
                for (int nt = 0; nt < 4; nt++) {
                    mma8(accU[mt][nt], au[mt], bo[nt]);
                    mma8(accX[mt][nt], ax[mt], bg[nt]);
                }
        }
        __syncthreads();
    }

    int crow = lane >> 2, ccol = (lane & 3) * 2;
    #pragma unroll
    for (int mt = 0; mt < 4; mt++) {
        #pragma unroll
        for (int nt = 0; nt < 4; nt++) {
            size_t r1 = i0 + wm + mt*16 + crow;
            int col = wn + nt*8 + ccol;
            float2 v0, v1;
            v0.x = accU[mt][nt][0] * sigm(accX[mt][nt][0]);
            v0.y = accU[mt][nt][1] * sigm(accX[mt][nt][1]);
            v1.x = accU[mt][nt][2] * sigm(accX[mt][nt][2]);
            v1.y = accU[mt][nt][3] * sigm(accX[mt][nt][3]);
            *(float2*)(out + r1*CH + col) = v0;
            *(float2*)(out + (r1+8)*CH + col) = v1;
        }
    }
}

// ---------------------------------------------------------------- launch
extern "C" void kernel_launch(void* const* d_in, const int* in_sizes, int n_in,
                              void* d_out, int out_size)
{
    const float* pair     = (const float*)d_in[0];
    const float* mask     = (const float*)d_in[1];
    const float* ln1_w    = (const float*)d_in[2];
    const float* ln1_b    = (const float*)d_in[3];
    const float* proj_w   = (const float*)d_in[4];
    const float* gate_w   = (const float*)d_in[5];
    const float* ln2_w    = (const float*)d_in[6];
    const float* ln2_b    = (const float*)d_in[7];
    const float* out_w    = (const float*)d_in[8];
    const float* gating_w = (const float*)d_in[9];
    float* out = (float*)d_out;

    cudaFuncSetAttribute(k_projgate_mma, cudaFuncAttributeMaxDynamicSharedMemorySize, PG_SMEM);
    cudaFuncSetAttribute(k_einsum_mma,   cudaFuncAttributeMaxDynamicSharedMemorySize, DSMEM);
    cudaFuncSetAttribute(k_final_mma,    cudaFuncAttributeMaxDynamicSharedMemorySize, FN_SMEM);

    k_ln1<<<RTOT/8, 256>>>(pair, ln1_w, ln1_b);
    k_projgate_mma<<<dim3(4, RTOT/128), 256, PG_SMEM>>>(proj_w, gate_w, mask);
    k_einsum_mma<<<dim3(NTOK/128, NTOK/128, CH), 256, DSMEM>>>();
    k_ln2t<<<RTOT/32, 256>>>(ln2_w, ln2_b);
    k_final_mma<<<RTOT/128, 256, FN_SMEM>>>(out_w, gating_w, out);
}

// round 8
// speedup vs baseline: 3.6132x; 1.9546x over previous
#include <cuda_runtime.h>
#include <cuda_fp16.h>
#include <math.h>
#include <stdint.h>

// TriangleMultiplication: N=768, C=128
//   k_ln1          : x = LN(pair)                            -> g_x [r][c] f32
//   k_projgate_mma : a,b = split((x@Wp^T)*mask*sig(x@Wg^T))  -> g_a,g_b [c][r] fp16 (m16n8k16)
//   k_einsum_mma   : out_c = A_c @ B_c^T per channel (fp16 mma) -> g_o [c][i][j] f32
//   k_ln2t         : u = LN_c(out) transposed                -> u (= g_ab reuse, f32) [r][c]
//   k_final_mma    : out = (u@Wo^T) * sig(x@Wgat^T) (tf32)   -> d_out

#define NTOK 768
#define CH   128
#define RTOT (NTOK*NTOK)   // 589824

__device__ float g_x[(size_t)RTOT*CH];
__device__ float g_o[(size_t)CH*RTOT];
__device__ __align__(256) unsigned char g_ab[(size_t)CH*RTOT*4];  // 2x half[CH*RTOT] OR float u[RTOT*CH]

__device__ __forceinline__ float sigm(float v){ return 1.f/(1.f+expf(-v)); }

__device__ __forceinline__ float tf32r(float x){
    uint32_t u;
    asm("cvt.rna.tf32.f32 %0, %1;" : "=r"(u) : "f"(x));
    return __uint_as_float(u);
}
__device__ __forceinline__ float4 tf32r4(float4 v){
    v.x = tf32r(v.x); v.y = tf32r(v.y); v.z = tf32r(v.z); v.w = tf32r(v.w);
    return v;
}

// fp16 m16n8k16 warp MMA (f32 accum)
__device__ __forceinline__ void mma16(float* d, const uint32_t* a, const uint32_t* b){
    asm volatile(
        "mma.sync.aligned.m16n8k16.row.col.f32.f16.f16.f32 "
        "{%0,%1,%2,%3}, {%4,%5,%6,%7}, {%8,%9}, {%0,%1,%2,%3};"
        : "+f"(d[0]), "+f"(d[1]), "+f"(d[2]), "+f"(d[3])
        : "r"(a[0]), "r"(a[1]), "r"(a[2]), "r"(a[3]), "r"(b[0]), "r"(b[1]));
}
// tf32 m16n8k8 warp MMA
__device__ __forceinline__ void mma8(float* d, const uint32_t* a, const uint32_t* b){
    asm volatile(
        "mma.sync.aligned.m16n8k8.row.col.f32.tf32.tf32.f32 "
        "{%0,%1,%2,%3}, {%4,%5,%6,%7}, {%8,%9}, {%0,%1,%2,%3};"
        : "+f"(d[0]), "+f"(d[1]), "+f"(d[2]), "+f"(d[3])
        : "r"(a[0]), "r"(a[1]), "r"(a[2]), "r"(a[3]), "r"(b[0]), "r"(b[1]));
}

__device__ __forceinline__ uint32_t h2u(__half2 h){
    uint32_t u;
    asm("mov.b32 %0, %1;" : "=r"(u) : "r"(*(uint32_t*)&h));
    return u;
}
// pack 8 floats -> 8 halves = 16 bytes (uint4)
__device__ __forceinline__ uint4 h8pack(float4 lo, float4 hi){
    uint4 r;
    __half2 a = __floats2half2_rn(lo.x, lo.y);
    __half2 b = __floats2half2_rn(lo.z, lo.w);
    __half2 c = __floats2half2_rn(hi.x, hi.y);
    __half2 d = __floats2half2_rn(hi.z, hi.w);
    r.x = *(uint32_t*)&a;
    r.y = *(uint32_t*)&b;
    r.z = *(uint32_t*)&c;
    r.w = *(uint32_t*)&d;
    return r;
}

#define ESTRIDE 36
#define TBUF (128*ESTRIDE)         // f32 tile (stride 36)
#define HSTRIDE 72
#define HBUF (128*HSTRIDE)         // fp16 tile: 128 rows x 64 halves (stride 72)

// ---------------------------------------------------------------- LN1
__global__ void k_ln1(const float* __restrict__ pair,
                      const float* __restrict__ w,
                      const float* __restrict__ b)
{
    int warp = threadIdx.x >> 5, lane = threadIdx.x & 31;
    size_t r = (size_t)blockIdx.x * 8 + warp;
    const float4* src = (const float4*)(pair + r * CH);
    float4 v = src[lane];
    float s = v.x + v.y + v.z + v.w;
    #pragma unroll
    for (int o = 16; o; o >>= 1) s += __shfl_xor_sync(0xffffffffu, s, o);
    float mu = s * (1.f/128.f);
    float dx = v.x-mu, dy = v.y-mu, dz = v.z-mu, dw = v.w-mu;
    float q = dx*dx + dy*dy + dz*dz + dw*dw;
    #pragma unroll
    for (int o = 16; o; o >>= 1) q += __shfl_xor_sync(0xffffffffu, q, o);
    float rstd = rsqrtf(q * (1.f/128.f) + 1e-5f);
    float4 wv = ((const float4*)w)[lane];
    float4 bv = ((const float4*)b)[lane];
    float4 o4;
    o4.x = dx*rstd*wv.x + bv.x;
    o4.y = dy*rstd*wv.y + bv.y;
    o4.z = dz*rstd*wv.z + bv.z;
    o4.w = dw*rstd*wv.w + bv.w;
    ((float4*)(g_x + r * CH))[lane] = o4;
}

// ---------------------------------------------------------------- proj+gate (fp16 mma)
// CTA: 128 rows x 128 virtual cols (jv = 4c+q : p0,p1,g0,g1). grid (4, RTOT/128).
// K=128 as 2 chunks of 64, double-buffered fp16 tiles.
#define PG_SMEM (4*HBUF*2)   // 2 bufs x (X,W) x 18432 B = 73728 B

__global__ void __launch_bounds__(256, 2) k_projgate_mma(
    const float* __restrict__ projw,
    const float* __restrict__ gatew,
    const float* __restrict__ mask)
{
    extern __shared__ __half hsm[];
    __shared__ float m_s[128];
    int tid = threadIdx.x, lane = tid & 31, warp = tid >> 5;
    int cg = blockIdx.x;
    size_t i0 = (size_t)blockIdx.y * 128;
    const float* A = g_x + i0 * CH;
    __half* ga = (__half*)g_ab;
    __half* gb = ga + (size_t)CH*RTOT;

    if (tid < 128) m_s[tid] = mask[(int)(i0 % NTOK) + tid];

    int wm = (warp >> 2) * 64;
    int wn = (warp & 3) * 32;

    float acc[4][4][4];
    #pragma unroll
    for (int mt = 0; mt < 4; mt++)
        #pragma unroll
        for (int nt = 0; nt < 4; nt++)
            #pragma unroll
            for (int e = 0; e < 4; e++) acc[mt][nt][e] = 0.f;

    int rr = tid >> 3, q8 = tid & 7;
    const float* wp[4];
    #pragma unroll
    for (int l = 0; l < 4; l++) {
        int jv = cg*128 + rr + l*32;
        int c = jv >> 2, q = jv & 3;
        wp[l] = (q < 2) ? (projw + (size_t)(2*c+q)*CH)
                        : (gatew + (size_t)(2*c+q-2)*CH);
    }

    // prologue: chunk 0 (k 0..63) -> buffer 0
    {
        __half* dX = hsm;
        __half* dW = hsm + HBUF;
        #pragma unroll
        for (int l = 0; l < 4; l++) {
            int r = rr + l*32;
            float4 lo = *(const float4*)(A + (size_t)r*CH + q8*8);
            float4 hi = *(const float4*)(A + (size_t)r*CH + q8*8 + 4);
            *(uint4*)(dX + r*HSTRIDE + q8*8) = h8pack(lo, hi);
            float4 wlo = *(const float4*)(wp[l] + q8*8);
            float4 whi = *(const float4*)(wp[l] + q8*8 + 4);
            *(uint4*)(dW + r*HSTRIDE + q8*8) = h8pack(wlo, whi);
        }
    }
    __syncthreads();

    int arow = lane >> 2, acol2 = (lane & 3) * 2;

    #pragma unroll
    for (int kc = 0; kc < 2; kc++) {
        int buf = kc & 1;
        if (kc + 1 < 2) {
            __half* dX = hsm + (buf^1)*2*HBUF;
            __half* dW = dX + HBUF;
            int k0 = 64;
            #pragma unroll
            for (int l = 0; l < 4; l++) {
                int r = rr + l*32;
                float4 lo = *(const float4*)(A + (size_t)r*CH + k0 + q8*8);
                float4 hi = *(const float4*)(A + (size_t)r*CH + k0 + q8*8 + 4);
                *(uint4*)(dX + r*HSTRIDE + q8*8) = h8pack(lo, hi);
                float4 wlo = *(const float4*)(wp[l] + k0 + q8*8);
                float4 whi = *(const float4*)(wp[l] + k0 + q8*8 + 4);
                *(uint4*)(dW + r*HSTRIDE + q8*8) = h8pack(wlo, whi);
            }
        }
        const __half* cX = hsm + buf*2*HBUF;
        const __half* cW = cX + HBUF;
        #pragma unroll
        for (int ks = 0; ks < 4; ks++) {
            int kb = ks * 16;
            uint32_t af[4][4], bf[4][2];
            #pragma unroll
            for (int mt = 0; mt < 4; mt++) {
                const __half* base = cX + (wm + mt*16 + arow)*HSTRIDE + kb + acol2;
                af[mt][0] = *(const uint32_t*)(base);
                af[mt][1] = *(const uint32_t*)(base + 8*HSTRIDE);
                af[mt][2] = *(const uint32_t*)(base + 8);
                af[mt][3] = *(const uint32_t*)(base + 8*HSTRIDE + 8);
            }
            #pragma unroll
            for (int nt = 0; nt < 4; nt++) {
                const __half* base = cW + (wn + nt*8 + arow)*HSTRIDE + kb + acol2;
                bf[nt][0] = *(const uint32_t*)(base);
                bf[nt][1] = *(const uint32_t*)(base + 8);
            }
            #pragma unroll
            for (int mt = 0; mt < 4; mt++)
                #pragma unroll
                for (int nt = 0; nt < 4; nt++)
                    mma16(acc[mt][nt], af[mt], bf[nt]);
        }
        __syncthreads();
    }

    // epilogue: even lanes hold (p0,p1); odd lanes hold (g0,g1).
    float* a_s = (float*)hsm;        // [32][132] f32
    float* b_s = a_s + 32*132;
    int crow = lane >> 2, ccol = (lane & 3) * 2;
    #pragma unroll
    for (int mt = 0; mt < 4; mt++) {
        #pragma unroll
        for (int nt = 0; nt < 4; nt++) {
            float g0r1 = __shfl_xor_sync(0xffffffffu, acc[mt][nt][0], 1);
            float g1r1 = __shfl_xor_sync(0xffffffffu, acc[mt][nt][1], 1);
            float g0r2 = __shfl_xor_sync(0xffffffffu, acc[mt][nt][2], 1);
            float g1r2 = __shfl_xor_sync(0xffffffffu, acc[mt][nt][3], 1);
            if ((lane & 1) == 0) {
                int j  = wn + nt*8 + ccol;
                int cl = j >> 2;
                int r1 = wm + mt*16 + crow, r2 = r1 + 8;
                float mk1 = m_s[r1], mk2 = m_s[r2];
                a_s[cl*132 + r1] = acc[mt][nt][0] * mk1 * sigm(g0r1);
                b_s[cl*132 + r1] = acc[mt][nt][1] * mk1 * sigm(g1r1);
                a_s[cl*132 + r2] = acc[mt][nt][2] * mk2 * sigm(g0r2);
                b_s[cl*132 + r2] = acc[mt][nt][3] * mk2 * sigm(g1r2);
            }
        }
    }
    __syncthreads();
    int cb = cg * 32;
    #pragma unroll
    for (int it = 0; it < 2; it++) {
        int idx = tid + it*256;              // 0..511 : ch(0..31) x f8(0..15)
        int ch = idx >> 4, f8 = idx & 15;
        float4 alo = *(float4*)(a_s + ch*132 + f8*8);
        float4 ahi = *(float4*)(a_s + ch*132 + f8*8 + 4);
        float4 blo = *(float4*)(b_s + ch*132 + f8*8);
        float4 bhi = *(float4*)(b_s + ch*132 + f8*8 + 4);
        *(uint4*)(ga + (size_t)(cb+ch)*RTOT + i0 + f8*8) = h8pack(alo, ahi);
        *(uint4*)(gb + (size_t)(cb+ch)*RTOT + i0 + f8*8) = h8pack(blo, bhi);
    }
}

// ---------------------------------------------------------------- fp16 mma einsum
// per channel: C = A(128x768)@B(128x768)^T; K-chunks of 64, double-buffered.
#define KC 64
#define NCHUNK (NTOK/KC)           // 12
#define DSMEM (4*HBUF*2)           // 73728 B

__global__ void __launch_bounds__(256, 2) k_einsum_mma()
{
    extern __shared__ __half hsm[];
    int c  = blockIdx.z;
    int i0 = blockIdx.y * 128;
    int j0 = blockIdx.x * 128;
    const __half* ga = (const __half*)g_ab;
    const __half* gb = ga + (size_t)CH*RTOT;
    const __half* A = ga + (size_t)c*RTOT + (size_t)i0*NTOK;
    const __half* B = gb + (size_t)c*RTOT + (size_t)j0*NTOK;
    float*        O = g_o + (size_t)c*RTOT;

    int tid = threadIdx.x, lane = tid & 31, warp = tid >> 5;
    int wm = (warp >> 2) * 64;
    int wn = (warp & 3) * 32;

    float acc[4][4][4];
    #pragma unroll
    for (int mt = 0; mt < 4; mt++)
        #pragma unroll
        for (int nt = 0; nt < 4; nt++)
            #pragma unroll
            for (int e = 0; e < 4; e++) acc[mt][nt][e] = 0.f;

    int rr = tid >> 3, q = tid & 7;

    {
        __half* dA = hsm;
        __half* dB = hsm + HBUF;
        #pragma unroll
        for (int l = 0; l < 4; l++) {
            int r = rr + l*32;
            *(uint4*)(dA + r*HSTRIDE + q*8) = *(const uint4*)(A + (size_t)r*NTOK + q*8);
            *(uint4*)(dB + r*HSTRIDE + q*8) = *(const uint4*)(B + (size_t)r*NTOK + q*8);
        }
    }
    __syncthreads();

    int arow = lane >> 2, acol2 = (lane & 3) * 2;

    for (int kc = 0; kc < NCHUNK; kc++) {
        int buf = kc & 1;
        if (kc + 1 < NCHUNK) {
            __half* dA = hsm + (buf^1)*2*HBUF;
            __half* dB = dA + HBUF;
            const __half* As = A + (kc+1)*KC;
            const __half* Bs = B + (kc+1)*KC;
            #pragma unroll
            for (int l = 0; l < 4; l++) {
                int r = rr + l*32;
                *(uint4*)(dA + r*HSTRIDE + q*8) = *(const uint4*)(As + (size_t)r*NTOK + q*8);
                *(uint4*)(dB + r*HSTRIDE + q*8) = *(const uint4*)(Bs + (size_t)r*NTOK + q*8);
            }
        }
        const __half* cA = hsm + buf*2*HBUF;
        const __half* cB = cA + HBUF;
        #pragma unroll
        for (int ks = 0; ks < 4; ks++) {
            int kb = ks * 16;
            uint32_t af[4][4], bf[4][2];
            #pragma unroll
            for (int mt = 0; mt < 4; mt++) {
                const __half* base = cA + (wm + mt*16 + arow)*HSTRIDE + kb + acol2;
                af[mt][0] = *(const uint32_t*)(base);
                af[mt][1] = *(const uint32_t*)(base + 8*HSTRIDE);
                af[mt][2] = *(const uint32_t*)(base + 8);
                af[mt][3] = *(const uint32_t*)(base + 8*HSTRIDE + 8);
            }
            #pragma unroll
            for (int nt = 0; nt < 4; nt++) {
                const __half* base = cB + (wn + nt*8 + arow)*HSTRIDE + kb + acol2;
                bf[nt][0] = *(const uint32_t*)(base);
                bf[nt][1] = *(const uint32_t*)(base + 8);
            }
            #pragma unroll
            for (int mt = 0; mt < 4; mt++)
                #pragma unroll
                for (int nt = 0; nt < 4; nt++)
                    mma16(acc[mt][nt], af[mt], bf[nt]);
        }
        __syncthreads();
    }

    int crow = lane >> 2, ccol = (lane & 3) * 2;
    #pragma unroll
    for (int mt = 0; mt < 4; mt++) {
        #pragma unroll
        for (int nt = 0; nt < 4; nt++) {
            float* d0 = O + (size_t)(i0 + wm + mt*16 + crow)*NTOK + j0 + wn + nt*8 + ccol;
            float2 v0; v0.x = acc[mt][nt][0]; v0.y = acc[mt][nt][1];
            float2 v1; v1.x = acc[mt][nt][2]; v1.y = acc[mt][nt][3];
            *(float2*)d0 = v0;
            *(float2*)(d0 + 8*NTOK) = v1;
        }
    }
}

// ---------------------------------------------------------------- LN2 + transpose
__global__ void k_ln2t(const float* __restrict__ w, const float* __restrict__ b)
{
    __shared__ float t[128*33];
    __shared__ float red[8][33];
    __shared__ float mu_s[32], rstd_s[32];
    int tid = threadIdx.x;
    size_t r0 = (size_t)blockIdx.x * 32;

    for (int idx = tid; idx < CH*32; idx += 256) {
        int c = idx >> 5, rr = idx & 31;
        t[c*33 + rr] = g_o[(size_t)c*RTOT + r0 + rr];
    }
    __syncthreads();
    int rr = tid & 31, part = tid >> 5;
    float s = 0.f;
    for (int c = part*16; c < part*16 + 16; c++) s += t[c*33 + rr];
    red[part][rr] = s;
    __syncthreads();
    if (tid < 32) {
        float tot = 0.f;
        #pragma unroll
        for (int p = 0; p < 8; p++) tot += red[p][tid];
        mu_s[tid] = tot * (1.f/128.f);
    }
    __syncthreads();
    float mu = mu_s[rr], qv = 0.f;
    for (int c = part*16; c < part*16 + 16; c++) {
        float d = t[c*33 + rr] - mu; qv += d*d;
    }
    __syncthreads();
    red[part][rr] = qv;
    __syncthreads();
    if (tid < 32) {
        float tot = 0.f;
        #pragma unroll
        for (int p = 0; p < 8; p++) tot += red[p][tid];
        rstd_s[tid] = rsqrtf(tot * (1.f/128.f) + 1e-5f);
    }
    __syncthreads();
    float* u = (float*)g_ab;   // g_a/g_b dead: reuse as fp32 u buffer
    for (int idx = tid; idx < CH*32; idx += 256) {
        int rr2 = idx >> 7, c = idx & 127;
        float val = (t[c*33 + rr2] - mu_s[rr2]) * rstd_s[rr2] * w[c] + b[c];
        u[(r0 + rr2)*CH + c] = val;
    }
}

// ---------------------------------------------------------------- final (2 fused tf32 GEMMs)
#define FN_SMEM (8*TBUF*4)   // 147456 B

__global__ void __launch_bounds__(256, 1) k_final_mma(
    const float* __restrict__ outw,
    const float* __restrict__ gatingw,
    float* __restrict__ out)
{
    extern __shared__ float sm[];
    int tid = threadIdx.x, lane = tid & 31, warp = tid >> 5;
    size_t i0 = (size_t)blockIdx.x * 128;
    const float* U = (const float*)g_ab + i0 * CH;
    const float* X = g_x + i0 * CH;

    int wm = (warp >> 2) * 64;
    int wn = (warp & 3) * 32;

    float accU[4][4][4], accX[4][4][4];
    #pragma unroll
    for (int mt = 0; mt < 4; mt++)
        #pragma unroll
        for (int nt = 0; nt < 4; nt++)
            #pragma unroll
            for (int e = 0; e < 4; e++) { accU[mt][nt][e] = 0.f; accX[mt][nt][e] = 0.f; }

    int rr = tid >> 3, q8 = tid & 7;

    {
        float* d0 = sm;
        #pragma unroll
        for (int l = 0; l < 4; l++) {
            int r = rr + l*32;
            *(float4*)(d0 + 0*TBUF + r*ESTRIDE + q8*4) = tf32r4(*(const float4*)(U + (size_t)r*CH + q8*4));
            *(float4*)(d0 + 1*TBUF + r*ESTRIDE + q8*4) = tf32r4(*(const float4*)(X + (size_t)r*CH + q8*4));
            *(float4*)(d0 + 2*TBUF + r*ESTRIDE + q8*4) = tf32r4(*(const float4*)(outw + (size_t)r*CH + q8*4));
            *(float4*)(d0 + 3*TBUF + r*ESTRIDE + q8*4) = tf32r4(*(const float4*)(gatingw + (size_t)r*CH + q8*4));
        }
    }
    __syncthreads();

    int arow = lane >> 2, acol = lane & 3;

    #pragma unroll
    for (int kc = 0; kc < 4; kc++) {
        int buf = kc & 1;
        if (kc + 1 < 4) {
            float* d0 = sm + (buf^1)*4*TBUF;
            int k0 = (kc+1)*32;
            #pragma unroll
            for (int l = 0; l < 4; l++) {
                int r = rr + l*32;
                *(float4*)(d0 + 0*TBUF + r*ESTRIDE + q8*4) = tf32r4(*(const float4*)(U + (size_t)r*CH + k0 + q8*4));
                *(float4*)(d0 + 1*TBUF + r*ESTRIDE + q8*4) = tf32r4(*(const float4*)(X + (size_t)r*CH + k0 + q8*4));
                *(float4*)(d0 + 2*TBUF + r*ESTRIDE + q8*4) = tf32r4(*(const float4*)(outw + (size_t)r*CH + k0 + q8*4));
                *(float4*)(d0 + 3*TBUF + r*ESTRIDE + q8*4) = tf32r4(*(const float4*)(gatingw + (size_t)r*CH + k0 + q8*4));
            }
        }
        const float* cb = sm + buf*4*TBUF;
        #pragma unroll
        for (int ks = 0; ks < 4; ks++) {
            int kb = ks * 8;
            uint32_t au[4][4], ax[4][4], bo[4][2], bg[4][2];
            #pragma unroll
            for (int mt = 0; mt < 4; mt++) {
                const float* bu = cb + 0*TBUF + (wm + mt*16 + arow)*ESTRIDE + kb + acol;
                au[mt][0] = __float_as_uint(bu[0]);
                au[mt][1] = __float_as_uint(bu[8*ESTRIDE]);
                au[mt][2] = __float_as_uint(bu[4]);
                au[mt][3] = __float_as_uint(bu[8*ESTRIDE + 4]);
                const float* bx = cb + 1*TBUF + (wm + mt*16 + arow)*ESTRIDE + kb + acol;
                ax[mt][0] = __float_as_uint(bx[0]);
                ax[mt][1] = __float_as_uint(bx[8*ESTRIDE]);
                ax[mt][2] = __float_as_uint(bx[4]);
                ax[mt][3] = __float_as_uint(bx[8*ESTRIDE + 4]);
            }
            #pragma unroll
            for (int nt = 0; nt < 4; nt++) {
                const float* po = cb + 2*TBUF + (wn + nt*8 + arow)*ESTRIDE + kb + acol;
                bo[nt][0] = __float_as_uint(po[0]);
                bo[nt][1] = __float_as_uint(po[4]);
                const float* pg = cb + 3*TBUF + (wn + nt*8 + arow)*ESTRIDE + kb + acol;
                bg[nt][0] = __float_as_uint(pg[0]);
                bg[nt][1] = __float_as_uint(pg[4]);
            }
            #pragma unroll
            for (int mt = 0; mt < 4; mt++)
                #pragma unroll
                for (int nt = 0; nt < 4; nt++) {
                    mma8(accU[mt][nt], au[mt], bo[nt]);
                    mma8(accX[mt][nt], ax[mt], bg[nt]);
                }
        }
        __syncthreads();
    }

    int crow = lane >> 2, ccol = (lane & 3) * 2;
    #pragma unroll
    for (int mt = 0; mt < 4; mt++) {
        #pragma unroll
        for (int nt = 0; nt < 4; nt++) {
            size_t r1 = i0 + wm + mt*16 + crow;
            int col = wn + nt*8 + ccol;
            float2 v0, v1;
            v0.x = accU[mt][nt][0] * sigm(accX[mt][nt][0]);
            v0.y = accU[mt][nt][1] * sigm(accX[mt][nt][1]);
            v1.x = accU[mt][nt][2] * sigm(accX[mt][nt][2]);
            v1.y = accU[mt][nt][3] * sigm(accX[mt][nt][3]);
            *(float2*)(out + r1*CH + col) = v0;
            *(float2*)(out + (r1+8)*CH + col) = v1;
        }
    }
}

// ---------------------------------------------------------------- launch
extern "C" void kernel_launch(void* const* d_in, const int* in_sizes, int n_in,
                              void* d_out, int out_size)
{
    const float* pair     = (const float*)d_in[0];
    const float* mask     = (const float*)d_in[1];
    const float* ln1_w    = (const float*)d_in[2];
    const float* ln1_b    = (const float*)d_in[3];
    const float* proj_w   = (const float*)d_in[4];
    const float* gate_w   = (const float*)d_in[5];
    const float* ln2_w    = (const float*)d_in[6];
    const float* ln2_b    = (const float*)d_in[7];
    const float* out_w    = (const float*)d_in[8];
    const float* gating_w = (const float*)d_in[9];
    float* out = (float*)d_out;

    cudaFuncSetAttribute(k_projgate_mma, cudaFuncAttributeMaxDynamicSharedMemorySize, PG_SMEM);
    cudaFuncSetAttribute(k_einsum_mma,   cudaFuncAttributeMaxDynamicSharedMemorySize, DSMEM);
    cudaFuncSetAttribute(k_final_mma,    cudaFuncAttributeMaxDynamicSharedMemorySize, FN_SMEM);

    k_ln1<<<RTOT/8, 256>>>(pair, ln1_w, ln1_b);
    k_projgate_mma<<<dim3(4, RTOT/128), 256, PG_SMEM>>>(proj_w, gate_w, mask);
    k_einsum_mma<<<dim3(NTOK/128, NTOK/128, CH), 256, DSMEM>>>();
    k_ln2t<<<RTOT/32, 256>>>(ln2_w, ln2_b);
    k_final_mma<<<RTOT/128, 256, FN_SMEM>>>(out_w, gating_w, out);
}

// round 9
// speedup vs baseline: 4.2988x; 1.1897x over previous
#include <cuda_runtime.h>
#include <cuda_fp16.h>
#include <math.h>
#include <stdint.h>

// TriangleMultiplication: N=768, C=128 — fp16 tensor-core pipeline
//   k_ln1          : x = LN(pair)                            -> g_xh [r][c] fp16
//   k_projgate_mma : a,b = split((x@Wp^T)*mask*sig(x@Wg^T))  -> ga,gb [c][r] fp16
//   k_einsum_mma   : out_c = A_c @ B_c^T per channel (fp16)  -> g_o [c][i][j] f32
//   k_ln2t         : u = LN_c(out) transposed                -> u (= g_ab reuse) fp16 [r][c]
//   k_final_mma    : out = (u@Wo^T) * sig(x@Wgat^T) (fp16)   -> d_out f32

#define NTOK 768
#define CH   128
#define RTOT (NTOK*NTOK)   // 589824

__device__ __half g_xh[(size_t)RTOT*CH];
__device__ float  g_o[(size_t)CH*RTOT];
__device__ __align__(256) unsigned char g_ab[(size_t)CH*RTOT*4];  // 2x half[CH*RTOT]; later half u[RTOT*CH]

__device__ __forceinline__ float sigm(float v){ return 1.f/(1.f+expf(-v)); }

// fp16 m16n8k16 warp MMA (f32 accum)
__device__ __forceinline__ void mma16(float* d, const uint32_t* a, const uint32_t* b){
    asm volatile(
        "mma.sync.aligned.m16n8k16.row.col.f32.f16.f16.f32 "
        "{%0,%1,%2,%3}, {%4,%5,%6,%7}, {%8,%9}, {%0,%1,%2,%3};"
        : "+f"(d[0]), "+f"(d[1]), "+f"(d[2]), "+f"(d[3])
        : "r"(a[0]), "r"(a[1]), "r"(a[2]), "r"(a[3]), "r"(b[0]), "r"(b[1]));
}

// pack 8 floats -> 8 halves = 16 bytes
__device__ __forceinline__ uint4 h8pack(float4 lo, float4 hi){
    uint4 r;
    __half2 a = __floats2half2_rn(lo.x, lo.y);
    __half2 b = __floats2half2_rn(lo.z, lo.w);
    __half2 c = __floats2half2_rn(hi.x, hi.y);
    __half2 d = __floats2half2_rn(hi.z, hi.w);
    r.x = *(uint32_t*)&a;
    r.y = *(uint32_t*)&b;
    r.z = *(uint32_t*)&c;
    r.w = *(uint32_t*)&d;
    return r;
}
// pack 4 floats -> 4 halves = 8 bytes
__device__ __forceinline__ uint2 h4pack(float4 v){
    uint2 r;
    __half2 a = __floats2half2_rn(v.x, v.y);
    __half2 b = __floats2half2_rn(v.z, v.w);
    r.x = *(uint32_t*)&a;
    r.y = *(uint32_t*)&b;
    return r;
}

#define HSTRIDE 72
#define HBUF (128*HSTRIDE)         // fp16 tile: 128 rows x 64 halves (stride 72)

// ---------------------------------------------------------------- LN1 -> fp16 x
__global__ void k_ln1(const float* __restrict__ pair,
                      const float* __restrict__ w,
                      const float* __restrict__ b)
{
    int warp = threadIdx.x >> 5, lane = threadIdx.x & 31;
    size_t r = (size_t)blockIdx.x * 8 + warp;
    const float4* src = (const float4*)(pair + r * CH);
    float4 v = src[lane];
    float s = v.x + v.y + v.z + v.w;
    #pragma unroll
    for (int o = 16; o; o >>= 1) s += __shfl_xor_sync(0xffffffffu, s, o);
    float mu = s * (1.f/128.f);
    float dx = v.x-mu, dy = v.y-mu, dz = v.z-mu, dw = v.w-mu;
    float q = dx*dx + dy*dy + dz*dz + dw*dw;
    #pragma unroll
    for (int o = 16; o; o >>= 1) q += __shfl_xor_sync(0xffffffffu, q, o);
    float rstd = rsqrtf(q * (1.f/128.f) + 1e-5f);
    float4 wv = ((const float4*)w)[lane];
    float4 bv = ((const float4*)b)[lane];
    float4 o4;
    o4.x = dx*rstd*wv.x + bv.x;
    o4.y = dy*rstd*wv.y + bv.y;
    o4.z = dz*rstd*wv.z + bv.z;
    o4.w = dw*rstd*wv.w + bv.w;
    *(uint2*)(g_xh + r * CH + lane*4) = h4pack(o4);
}

// ---------------------------------------------------------------- proj+gate (fp16 mma)
// CTA: 128 rows x 128 virtual cols (jv = 4c+q : p0,p1,g0,g1). grid (4, RTOT/128).
#define PG_SMEM (4*HBUF*2)   // 73728 B

__global__ void __launch_bounds__(256, 2) k_projgate_mma(
    const float* __restrict__ projw,
    const float* __restrict__ gatew,
    const float* __restrict__ mask)
{
    extern __shared__ __half hsm[];
    __shared__ float m_s[128];
    int tid = threadIdx.x, lane = tid & 31, warp = tid >> 5;
    int cg = blockIdx.x;
    size_t i0 = (size_t)blockIdx.y * 128;
    const __half* A = g_xh + i0 * CH;
    __half* ga = (__half*)g_ab;
    __half* gb = ga + (size_t)CH*RTOT;

    if (tid < 128) m_s[tid] = mask[(int)(i0 % NTOK) + tid];

    int wm = (warp >> 2) * 64;
    int wn = (warp & 3) * 32;

    float acc[4][4][4];
    #pragma unroll
    for (int mt = 0; mt < 4; mt++)
        #pragma unroll
        for (int nt = 0; nt < 4; nt++)
            #pragma unroll
            for (int e = 0; e < 4; e++) acc[mt][nt][e] = 0.f;

    int rr = tid >> 3, q8 = tid & 7;
    const float* wp[4];
    #pragma unroll
    for (int l = 0; l < 4; l++) {
        int jv = cg*128 + rr + l*32;
        int c = jv >> 2, q = jv & 3;
        wp[l] = (q < 2) ? (projw + (size_t)(2*c+q)*CH)
                        : (gatew + (size_t)(2*c+q-2)*CH);
    }

    // prologue: chunk 0 (k 0..63) -> buffer 0
    {
        __half* dX = hsm;
        __half* dW = hsm + HBUF;
        #pragma unroll
        for (int l = 0; l < 4; l++) {
            int r = rr + l*32;
            *(uint4*)(dX + r*HSTRIDE + q8*8) = *(const uint4*)(A + (size_t)r*CH + q8*8);
            float4 wlo = *(const float4*)(wp[l] + q8*8);
            float4 whi = *(const float4*)(wp[l] + q8*8 + 4);
            *(uint4*)(dW + r*HSTRIDE + q8*8) = h8pack(wlo, whi);
        }
    }
    __syncthreads();

    int arow = lane >> 2, acol2 = (lane & 3) * 2;

    #pragma unroll
    for (int kc = 0; kc < 2; kc++) {
        int buf = kc & 1;
        if (kc + 1 < 2) {
            __half* dX = hsm + (buf^1)*2*HBUF;
            __half* dW = dX + HBUF;
            int k0 = 64;
            #pragma unroll
            for (int l = 0; l < 4; l++) {
                int r = rr + l*32;
                *(uint4*)(dX + r*HSTRIDE + q8*8) = *(const uint4*)(A + (size_t)r*CH + k0 + q8*8);
                float4 wlo = *(const float4*)(wp[l] + k0 + q8*8);
                float4 whi = *(const float4*)(wp[l] + k0 + q8*8 + 4);
                *(uint4*)(dW + r*HSTRIDE + q8*8) = h8pack(wlo, whi);
            }
        }
        const __half* cX = hsm + buf*2*HBUF;
        const __half* cW = cX + HBUF;
        #pragma unroll
        for (int ks = 0; ks < 4; ks++) {
            int kb = ks * 16;
            uint32_t af[4][4], bf[4][2];
            #pragma unroll
            for (int mt = 0; mt < 4; mt++) {
                const __half* base = cX + (wm + mt*16 + arow)*HSTRIDE + kb + acol2;
                af[mt][0] = *(const uint32_t*)(base);
                af[mt][1] = *(const uint32_t*)(base + 8*HSTRIDE);
                af[mt][2] = *(const uint32_t*)(base + 8);
                af[mt][3] = *(const uint32_t*)(base + 8*HSTRIDE + 8);
            }
            #pragma unroll
            for (int nt = 0; nt < 4; nt++) {
                const __half* base = cW + (wn + nt*8 + arow)*HSTRIDE + kb + acol2;
                bf[nt][0] = *(const uint32_t*)(base);
                bf[nt][1] = *(const uint32_t*)(base + 8);
            }
            #pragma unroll
            for (int mt = 0; mt < 4; mt++)
                #pragma unroll
                for (int nt = 0; nt < 4; nt++)
                    mma16(acc[mt][nt], af[mt], bf[nt]);
        }
        __syncthreads();
    }

    // epilogue: even lanes hold (p0,p1); odd lanes hold (g0,g1).
    float* a_s = (float*)hsm;        // [32][132] f32
    float* b_s = a_s + 32*132;
    int crow = lane >> 2, ccol = (lane & 3) * 2;
    #pragma unroll
    for (int mt = 0; mt < 4; mt++) {
        #pragma unroll
        for (int nt = 0; nt < 4; nt++) {
            float g0r1 = __shfl_xor_sync(0xffffffffu, acc[mt][nt][0], 1);
            float g1r1 = __shfl_xor_sync(0xffffffffu, acc[mt][nt][1], 1);
            float g0r2 = __shfl_xor_sync(0xffffffffu, acc[mt][nt][2], 1);
            float g1r2 = __shfl_xor_sync(0xffffffffu, acc[mt][nt][3], 1);
            if ((lane & 1) == 0) {
                int j  = wn + nt*8 + ccol;
                int cl = j >> 2;
                int r1 = wm + mt*16 + crow, r2 = r1 + 8;
                float mk1 = m_s[r1], mk2 = m_s[r2];
                a_s[cl*132 + r1] = acc[mt][nt][0] * mk1 * sigm(g0r1);
                b_s[cl*132 + r1] = acc[mt][nt][1] * mk1 * sigm(g1r1);
                a_s[cl*132 + r2] = acc[mt][nt][2] * mk2 * sigm(g0r2);
                b_s[cl*132 + r2] = acc[mt][nt][3] * mk2 * sigm(g1r2);
            }
        }
    }
    __syncthreads();
    int cb = cg * 32;
    #pragma unroll
    for (int it = 0; it < 2; it++) {
        int idx = tid + it*256;              // 0..511 : ch(0..31) x f8(0..15)
        int ch = idx >> 4, f8 = idx & 15;
        float4 alo = *(float4*)(a_s + ch*132 + f8*8);
        float4 ahi = *(float4*)(a_s + ch*132 + f8*8 + 4);
        float4 blo = *(float4*)(b_s + ch*132 + f8*8);
        float4 bhi = *(float4*)(b_s + ch*132 + f8*8 + 4);
        *(uint4*)(ga + (size_t)(cb+ch)*RTOT + i0 + f8*8) = h8pack(alo, ahi);
        *(uint4*)(gb + (size_t)(cb+ch)*RTOT + i0 + f8*8) = h8pack(blo, bhi);
    }
}

// ---------------------------------------------------------------- fp16 mma einsum
#define KC 64
#define NCHUNK (NTOK/KC)           // 12
#define DSMEM (4*HBUF*2)           // 73728 B

__global__ void __launch_bounds__(256, 2) k_einsum_mma()
{
    extern __shared__ __half hsm[];
    int c  = blockIdx.z;
    int i0 = blockIdx.y * 128;
    int j0 = blockIdx.x * 128;
    const __half* ga = (const __half*)g_ab;
    const __half* gb = ga + (size_t)CH*RTOT;
    const __half* A = ga + (size_t)c*RTOT + (size_t)i0*NTOK;
    const __half* B = gb + (size_t)c*RTOT + (size_t)j0*NTOK;
    float*        O = g_o + (size_t)c*RTOT;

    int tid = threadIdx.x, lane = tid & 31, warp = tid >> 5;
    int wm = (warp >> 2) * 64;
    int wn = (warp & 3) * 32;

    float acc[4][4][4];
    #pragma unroll
    for (int mt = 0; mt < 4; mt++)
        #pragma unroll
        for (int nt = 0; nt < 4; nt++)
            #pragma unroll
            for (int e = 0; e < 4; e++) acc[mt][nt][e] = 0.f;

    int rr = tid >> 3, q = tid & 7;

    {
        __half* dA = hsm;
        __half* dB = hsm + HBUF;
        #pragma unroll
        for (int l = 0; l < 4; l++) {
            int r = rr + l*32;
            *(uint4*)(dA + r*HSTRIDE + q*8) = *(const uint4*)(A + (size_t)r*NTOK + q*8);
            *(uint4*)(dB + r*HSTRIDE + q*8) = *(const uint4*)(B + (size_t)r*NTOK + q*8);
        }
    }
    __syncthreads();

    int arow = lane >> 2, acol2 = (lane & 3) * 2;

    for (int kc = 0; kc < NCHUNK; kc++) {
        int buf = kc & 1;
        if (kc + 1 < NCHUNK) {
            __half* dA = hsm + (buf^1)*2*HBUF;
            __half* dB = dA + HBUF;
            const __half* As = A + (kc+1)*KC;
            const __half* Bs = B + (kc+1)*KC;
            #pragma unroll
            for (int l = 0; l < 4; l++) {
                int r = rr + l*32;
                *(uint4*)(dA + r*HSTRIDE + q*8) = *(const uint4*)(As + (size_t)r*NTOK + q*8);
                *(uint4*)(dB + r*HSTRIDE + q*8) = *(const uint4*)(Bs + (size_t)r*NTOK + q*8);
            }
        }
        const __half* cA = hsm + buf*2*HBUF;
        const __half* cB = cA + HBUF;
        #pragma unroll
        for (int ks = 0; ks < 4; ks++) {
            int kb = ks * 16;
            uint32_t af[4][4], bf[4][2];
            #pragma unroll
            for (int mt = 0; mt < 4; mt++) {
                const __half* base = cA + (wm + mt*16 + arow)*HSTRIDE + kb + acol2;
                af[mt][0] = *(const uint32_t*)(base);
                af[mt][1] = *(const uint32_t*)(base + 8*HSTRIDE);
                af[mt][2] = *(const uint32_t*)(base + 8);
                af[mt][3] = *(const uint32_t*)(base + 8*HSTRIDE + 8);
            }
            #pragma unroll
            for (int nt = 0; nt < 4; nt++) {
                const __half* base = cB + (wn + nt*8 + arow)*HSTRIDE + kb + acol2;
                bf[nt][0] = *(const uint32_t*)(base);
                bf[nt][1] = *(const uint32_t*)(base + 8);
            }
            #pragma unroll
            for (int mt = 0; mt < 4; mt++)
                #pragma unroll
                for (int nt = 0; nt < 4; nt++)
                    mma16(acc[mt][nt], af[mt], bf[nt]);
        }
        __syncthreads();
    }

    int crow = lane >> 2, ccol = (lane & 3) * 2;
    #pragma unroll
    for (int mt = 0; mt < 4; mt++) {
        #pragma unroll
        for (int nt = 0; nt < 4; nt++) {
            float* d0 = O + (size_t)(i0 + wm + mt*16 + crow)*NTOK + j0 + wn + nt*8 + ccol;
            float2 v0; v0.x = acc[mt][nt][0]; v0.y = acc[mt][nt][1];
            float2 v1; v1.x = acc[mt][nt][2]; v1.y = acc[mt][nt][3];
            *(float2*)d0 = v0;
            *(float2*)(d0 + 8*NTOK) = v1;
        }
    }
}

// ---------------------------------------------------------------- LN2 + transpose (vectorized, fp16 out)
__global__ void k_ln2t(const float* __restrict__ w, const float* __restrict__ b)
{
    __shared__ float t[128*36];
    __shared__ float red[8][33];
    __shared__ float mu_s[32], rstd_s[32];
    __shared__ float w_s[128], b_s[128];
    int tid = threadIdx.x;
    size_t r0 = (size_t)blockIdx.x * 32;

    if (tid < 128) { w_s[tid] = w[tid]; b_s[tid] = b[tid]; }

    #pragma unroll
    for (int it = 0; it < 4; it++) {
        int idx = tid + it*256;            // 0..1023 : c(0..127) x rq(0..7)
        int c = idx >> 3, rq = idx & 7;
        *(float4*)(t + c*36 + rq*4) = *(const float4*)(g_o + (size_t)c*RTOT + r0 + rq*4);
    }
    __syncthreads();

    int rr = tid & 31, part = tid >> 5;
    float s = 0.f;
    #pragma unroll
    for (int k = 0; k < 16; k++) s += t[(part*16 + k)*36 + rr];
    red[part][rr] = s;
    __syncthreads();
    if (tid < 32) {
        float tot = 0.f;
        #pragma unroll
        for (int p = 0; p < 8; p++) tot += red[p][tid];
        mu_s[tid] = tot * (1.f/128.f);
    }
    __syncthreads();
    float mu = mu_s[rr], qv = 0.f;
    #pragma unroll
    for (int k = 0; k < 16; k++) {
        float d = t[(part*16 + k)*36 + rr] - mu; qv += d*d;
    }
    __syncthreads();
    red[part][rr] = qv;
    __syncthreads();
    if (tid < 32) {
        float tot = 0.f;
        #pragma unroll
        for (int p = 0; p < 8; p++) tot += red[p][tid];
        rstd_s[tid] = rsqrtf(tot * (1.f/128.f) + 1e-5f);
    }
    __syncthreads();

    float rstd = rstd_s[rr];
    mu = mu_s[rr];
    __half* u = (__half*)g_ab;   // ga/gb dead: reuse as fp16 u buffer [r][c]
    float f[16];
    #pragma unroll
    for (int k = 0; k < 16; k++) {
        int c = part*16 + k;
        f[k] = (t[c*36 + rr] - mu) * rstd * w_s[c] + b_s[c];
    }
    __half* dst = u + (r0 + rr)*CH + part*16;
    *(uint4*)(dst)     = h8pack(make_float4(f[0],f[1],f[2],f[3]),   make_float4(f[4],f[5],f[6],f[7]));
    *(uint4*)(dst + 8) = h8pack(make_float4(f[8],f[9],f[10],f[11]), make_float4(f[12],f[13],f[14],f[15]));
}

// ---------------------------------------------------------------- final (2 fused fp16 GEMMs)
// D1 = U @ OutW^T, D2 = X @ GatW^T; out = D1 * sig(D2). K=128 as 2 chunks of 64.
#define FN_SMEM (8*HBUF*2)   // 2 bufs x 4 tiles x 18432 B = 147456 B

__global__ void __launch_bounds__(256, 1) k_final_mma(
    const float* __restrict__ outw,
    const float* __restrict__ gatingw,
    float* __restrict__ out)
{
    extern __shared__ __half hsm[];
    int tid = threadIdx.x, lane = tid & 31, warp = tid >> 5;
    size_t i0 = (size_t)blockIdx.x * 128;
    const __half* U = (const __half*)g_ab + i0 * CH;
    const __half* X = g_xh + i0 * CH;

    int wm = (warp >> 2) * 64;
    int wn = (warp & 3) * 32;

    float accU[4][4][4], accX[4][4][4];
    #pragma unroll
    for (int mt = 0; mt < 4; mt++)
        #pragma unroll
        for (int nt = 0; nt < 4; nt++)
            #pragma unroll
            for (int e = 0; e < 4; e++) { accU[mt][nt][e] = 0.f; accX[mt][nt][e] = 0.f; }

    int rr = tid >> 3, q8 = tid & 7;

    // buffer b at hsm + b*4*HBUF; within: [U | X | Wo | Wg]
    {
        __half* d0 = hsm;
        #pragma unroll
        for (int l = 0; l < 4; l++) {
            int r = rr + l*32;
            *(uint4*)(d0 + 0*HBUF + r*HSTRIDE + q8*8) = *(const uint4*)(U + (size_t)r*CH + q8*8);
            *(uint4*)(d0 + 1*HBUF + r*HSTRIDE + q8*8) = *(const uint4*)(X + (size_t)r*CH + q8*8);
            float4 olo = *(const float4*)(outw + (size_t)r*CH + q8*8);
            float4 ohi = *(const float4*)(outw + (size_t)r*CH + q8*8 + 4);
            *(uint4*)(d0 + 2*HBUF + r*HSTRIDE + q8*8) = h8pack(olo, ohi);
            float4 glo = *(const float4*)(gatingw + (size_t)r*CH + q8*8);
            float4 ghi = *(const float4*)(gatingw + (size_t)r*CH + q8*8 + 4);
            *(uint4*)(d0 + 3*HBUF + r*HSTRIDE + q8*8) = h8pack(glo, ghi);
        }
    }
    __syncthreads();

    int arow = lane >> 2, acol2 = (lane & 3) * 2;

    #pragma unroll
    for (int kc = 0; kc < 2; kc++) {
        int buf = kc & 1;
        if (kc + 1 < 2) {
            __half* d0 = hsm + (buf^1)*4*HBUF;
            int k0 = 64;
            #pragma unroll
            for (int l = 0; l < 4; l++) {
                int r = rr + l*32;
                *(uint4*)(d0 + 0*HBUF + r*HSTRIDE + q8*8) = *(const uint4*)(U + (size_t)r*CH + k0 + q8*8);
                *(uint4*)(d0 + 1*HBUF + r*HSTRIDE + q8*8) = *(const uint4*)(X + (size_t)r*CH + k0 + q8*8);
                float4 olo = *(const float4*)(outw + (size_t)r*CH + k0 + q8*8);
                float4 ohi = *(const float4*)(outw + (size_t)r*CH + k0 + q8*8 + 4);
                *(uint4*)(d0 + 2*HBUF + r*HSTRIDE + q8*8) = h8pack(olo, ohi);
                float4 glo = *(const float4*)(gatingw + (size_t)r*CH + k0 + q8*8);
                float4 ghi = *(const float4*)(gatingw + (size_t)r*CH + k0 + q8*8 + 4);
                *(uint4*)(d0 + 3*HBUF + r*HSTRIDE + q8*8) = h8pack(glo, ghi);
            }
        }
        const __half* cb = hsm + buf*4*HBUF;
        #pragma unroll
        for (int ks = 0; ks < 4; ks++) {
            int kb = ks * 16;
            uint32_t au[4][4], ax[4][4], bo[4][2], bg[4][2];
            #pragma unroll
            for (int mt = 0; mt < 4; mt++) {
                const __half* bu = cb + 0*HBUF + (wm + mt*16 + arow)*HSTRIDE + kb + acol2;
                au[mt][0] = *(const uint32_t*)(bu);
                au[mt][1] = *(const uint32_t*)(bu + 8*HSTRIDE);
                au[mt][2] = *(const uint32_t*)(bu + 8);
                au[mt][3] = *(const uint32_t*)(bu + 8*HSTRIDE + 8);
                const __half* bx = cb + 1*HBUF + (wm + mt*16 + arow)*HSTRIDE + kb + acol2;
                ax[mt][0] = *(const uint32_t*)(bx);
                ax[mt][1] = *(const uint32_t*)(bx + 8*HSTRIDE);
                ax[mt][2] = *(const uint32_t*)(bx + 8);
                ax[mt][3] = *(const uint32_t*)(bx + 8*HSTRIDE + 8);
            }
            #pragma unroll
            for (int nt = 0; nt < 4; nt++) {
                const __half* po = cb + 2*HBUF + (wn + nt*8 + arow)*HSTRIDE + kb + acol2;
                bo[nt][0] = *(const uint32_t*)(po);
                bo[nt][1] = *(const uint32_t*)(po + 8);
                const __half* pg = cb + 3*HBUF + (wn + nt*8 + arow)*HSTRIDE + kb + acol2;
                bg[nt][0] = *(const uint32_t*)(pg);
                bg[nt][1] = *(const uint32_t*)(pg + 8);
            }
            #pragma unroll
            for (int mt = 0; mt < 4; mt++)
                #pragma unroll
                for (int nt = 0; nt < 4; nt++) {
                    mma16(accU[mt][nt], au[mt], bo[nt]);
                    mma16(accX[mt][nt], ax[mt], bg[nt]);
                }
        }
        __syncthreads();
    }

    int crow = lane >> 2, ccol = (lane & 3) * 2;
    #pragma unroll
    for (int mt = 0; mt < 4; mt++) {
        #pragma unroll
        for (int nt = 0; nt < 4; nt++) {
            size_t r1 = i0 + wm + mt*16 + crow;
            int col = wn + nt*8 + ccol;
            float2 v0, v1;
            v0.x = accU[mt][nt][0] * sigm(accX[mt][nt][0]);
            v0.y = accU[mt][nt][1] * sigm(accX[mt][nt][1]);
            v1.x = accU[mt][nt][2] * sigm(accX[mt][nt][2]);
            v1.y = accU[mt][nt][3] * sigm(accX[mt][nt][3]);
            *(float2*)(out + r1*CH + col) = v0;
            *(float2*)(out + (r1+8)*CH + col) = v1;
        }
    }
}

// ---------------------------------------------------------------- launch
extern "C" void kernel_launch(void* const* d_in, const int* in_sizes, int n_in,
                              void* d_out, int out_size)
{
    const float* pair     = (const float*)d_in[0];
    const float* mask     = (const float*)d_in[1];
    const float* ln1_w    = (const float*)d_in[2];
    const float* ln1_b    = (const float*)d_in[3];
    const float* proj_w   = (const float*)d_in[4];
    const float* gate_w   = (const float*)d_in[5];
    const float* ln2_w    = (const float*)d_in[6];
    const float* ln2_b    = (const float*)d_in[7];
    const float* out_w    = (const float*)d_in[8];
    const float* gating_w = (const float*)d_in[9];
    float* out = (float*)d_out;

    cudaFuncSetAttribute(k_projgate_mma, cudaFuncAttributeMaxDynamicSharedMemorySize, PG_SMEM);
    cudaFuncSetAttribute(k_einsum_mma,   cudaFuncAttributeMaxDynamicSharedMemorySize, DSMEM);
    cudaFuncSetAttribute(k_final_mma,    cudaFuncAttributeMaxDynamicSharedMemorySize, FN_SMEM);

    k_ln1<<<RTOT/8, 256>>>(pair, ln1_w, ln1_b);
    k_projgate_mma<<<dim3(4, RTOT/128), 256, PG_SMEM>>>(proj_w, gate_w, mask);
    k_einsum_mma<<<dim3(NTOK/128, NTOK/128, CH), 256, DSMEM>>>();
    k_ln2t<<<RTOT/32, 256>>>(ln2_w, ln2_b);
    k_final_mma<<<RTOT/128, 256, FN_SMEM>>>(out_w, gating_w, out);
}

// round 10
// speedup vs baseline: 4.5341x; 1.0547x over previous
#include <cuda_runtime.h>
#include <cuda_fp16.h>
#include <math.h>
#include <stdint.h>

// TriangleMultiplication: N=768, C=128 — fp16 tensor-core pipeline + cp.async
//   k_cvtw         : weights -> fp16 (g_wh: [512 pg-interleaved | 128 out_w | 128 gating_w])
//   k_ln1          : x = LN(pair)                            -> g_xh [r][c] fp16
//   k_projgate_mma : a,b = split((x@Wp^T)*mask*sig(x@Wg^T))  -> ga,gb [c][r] fp16
//   k_einsum_mma   : out_c = A_c @ B_c^T per channel (fp16)  -> g_o [c][i][j] f32
//   k_ln2t         : u = LN_c(out) transposed                -> u (= g_ab reuse) fp16 [r][c]
//   k_final_mma    : out = (u@Wo^T) * sig(x@Wgat^T) (fp16)   -> d_out f32

#define NTOK 768
#define CH   128
#define RTOT (NTOK*NTOK)   // 589824

__device__ __half g_xh[(size_t)RTOT*CH];
__device__ float  g_o[(size_t)CH*RTOT];
__device__ __align__(256) unsigned char g_ab[(size_t)CH*RTOT*4];  // 2x half[CH*RTOT]; later half u[RTOT*CH]
__device__ __half g_wh[768*CH];   // fp16 weights: [0,512)=proj/gate interleaved, [512,640)=out_w, [640,768)=gating_w

__device__ __forceinline__ float sigm(float v){ return 1.f/(1.f+expf(-v)); }

// fp16 m16n8k16 warp MMA (f32 accum)
__device__ __forceinline__ void mma16(float* d, const uint32_t* a, const uint32_t* b){
    asm volatile(
        "mma.sync.aligned.m16n8k16.row.col.f32.f16.f16.f32 "
        "{%0,%1,%2,%3}, {%4,%5,%6,%7}, {%8,%9}, {%0,%1,%2,%3};"
        : "+f"(d[0]), "+f"(d[1]), "+f"(d[2]), "+f"(d[3])
        : "r"(a[0]), "r"(a[1]), "r"(a[2]), "r"(a[3]), "r"(b[0]), "r"(b[1]));
}

// pack 8 floats -> 8 halves = 16 bytes
__device__ __forceinline__ uint4 h8pack(float4 lo, float4 hi){
    uint4 r;
    __half2 a = __floats2half2_rn(lo.x, lo.y);
    __half2 b = __floats2half2_rn(lo.z, lo.w);
    __half2 c = __floats2half2_rn(hi.x, hi.y);
    __half2 d = __floats2half2_rn(hi.z, hi.w);
    r.x = *(uint32_t*)&a;
    r.y = *(uint32_t*)&b;
    r.z = *(uint32_t*)&c;
    r.w = *(uint32_t*)&d;
    return r;
}
__device__ __forceinline__ uint2 h4pack(float4 v){
    uint2 r;
    __half2 a = __floats2half2_rn(v.x, v.y);
    __half2 b = __floats2half2_rn(v.z, v.w);
    r.x = *(uint32_t*)&a;
    r.y = *(uint32_t*)&b;
    return r;
}

// 16B async copy, L2-resident (.cg)
__device__ __forceinline__ void cpa16(__half* dst, const __half* src){
    uint32_t s;
    asm("{ .reg .u64 t; cvta.to.shared.u64 t, %1; cvt.u32.u64 %0, t; }" : "=r"(s) : "l"(dst));
    asm volatile("cp.async.cg.shared.global [%0], [%1], 16;" :: "r"(s), "l"(src));
}
#define CPA_COMMIT() asm volatile("cp.async.commit_group;" ::: "memory")
#define CPA_WAIT0()  asm volatile("cp.async.wait_group 0;" ::: "memory")

#define HSTRIDE 72
#define HBUF (128*HSTRIDE)         // fp16 tile: 128 rows x 64 halves (stride 72)

// ---------------------------------------------------------------- weight convert
__global__ void k_cvtw(const float* __restrict__ projw, const float* __restrict__ gatew,
                       const float* __restrict__ outw,  const float* __restrict__ gatingw)
{
    int idx = blockIdx.x*256 + threadIdx.x;   // 768 rows x 16 vec8 = 12288
    int row = idx >> 4, q8 = idx & 15;
    const float* src;
    if (row < 512) {
        int c = row >> 2, q = row & 3;
        src = (q < 2) ? projw + (size_t)(2*c+q)*CH : gatew + (size_t)(2*c+q-2)*CH;
    } else if (row < 640) {
        src = outw + (size_t)(row-512)*CH;
    } else {
        src = gatingw + (size_t)(row-640)*CH;
    }
    float4 lo = *(const float4*)(src + q8*8);
    float4 hi = *(const float4*)(src + q8*8 + 4);
    *(uint4*)(g_wh + (size_t)row*CH + q8*8) = h8pack(lo, hi);
}

// ---------------------------------------------------------------- LN1 -> fp16 x
__global__ void k_ln1(const float* __restrict__ pair,
                      const float* __restrict__ w,
                      const float* __restrict__ b)
{
    int warp = threadIdx.x >> 5, lane = threadIdx.x & 31;
    size_t r = (size_t)blockIdx.x * 8 + warp;
    const float4* src = (const float4*)(pair + r * CH);
    float4 v = src[lane];
    float s = v.x + v.y + v.z + v.w;
    #pragma unroll
    for (int o = 16; o; o >>= 1) s += __shfl_xor_sync(0xffffffffu, s, o);
    float mu = s * (1.f/128.f);
    float dx = v.x-mu, dy = v.y-mu, dz = v.z-mu, dw = v.w-mu;
    float q = dx*dx + dy*dy + dz*dz + dw*dw;
    #pragma unroll
    for (int o = 16; o; o >>= 1) q += __shfl_xor_sync(0xffffffffu, q, o);
    float rstd = rsqrtf(q * (1.f/128.f) + 1e-5f);
    float4 wv = ((const float4*)w)[lane];
    float4 bv = ((const float4*)b)[lane];
    float4 o4;
    o4.x = dx*rstd*wv.x + bv.x;
    o4.y = dy*rstd*wv.y + bv.y;
    o4.z = dz*rstd*wv.z + bv.z;
    o4.w = dw*rstd*wv.w + bv.w;
    *(uint2*)(g_xh + r * CH + lane*4) = h4pack(o4);
}

// ---------------------------------------------------------------- proj+gate (fp16 mma + cp.async)
#define PG_SMEM (4*HBUF*2)   // 73728 B

__global__ void __launch_bounds__(256, 2) k_projgate_mma(const float* __restrict__ mask)
{
    extern __shared__ __half hsm[];
    __shared__ float m_s[128];
    int tid = threadIdx.x, lane = tid & 31, warp = tid >> 5;
    int cg = blockIdx.x;
    size_t i0 = (size_t)blockIdx.y * 128;
    const __half* A = g_xh + i0 * CH;
    __half* ga = (__half*)g_ab;
    __half* gb = ga + (size_t)CH*RTOT;

    if (tid < 128) m_s[tid] = mask[(int)(i0 % NTOK) + tid];

    int wm = (warp >> 2) * 64;
    int wn = (warp & 3) * 32;

    float acc[4][4][4];
    #pragma unroll
    for (int mt = 0; mt < 4; mt++)
        #pragma unroll
        for (int nt = 0; nt < 4; nt++)
            #pragma unroll
            for (int e = 0; e < 4; e++) acc[mt][nt][e] = 0.f;

    int rr = tid >> 3, q8 = tid & 7;
    const __half* W = g_wh + (size_t)(cg*128) * CH;   // 128 interleaved virtual rows

    // prologue: chunk 0 (k 0..63) -> buffer 0
    {
        __half* dX = hsm;
        __half* dW = hsm + HBUF;
        #pragma unroll
        for (int l = 0; l < 4; l++) {
            int r = rr + l*32;
            cpa16(dX + r*HSTRIDE + q8*8, A + (size_t)r*CH + q8*8);
            cpa16(dW + r*HSTRIDE + q8*8, W + (size_t)r*CH + q8*8);
        }
        CPA_COMMIT(); CPA_WAIT0();
    }
    __syncthreads();

    int arow = lane >> 2, acol2 = (lane & 3) * 2;

    #pragma unroll
    for (int kc = 0; kc < 2; kc++) {
        int buf = kc & 1;
        if (kc + 1 < 2) {
            __half* dX = hsm + (buf^1)*2*HBUF;
            __half* dW = dX + HBUF;
            #pragma unroll
            for (int l = 0; l < 4; l++) {
                int r = rr + l*32;
                cpa16(dX + r*HSTRIDE + q8*8, A + (size_t)r*CH + 64 + q8*8);
                cpa16(dW + r*HSTRIDE + q8*8, W + (size_t)r*CH + 64 + q8*8);
            }
            CPA_COMMIT();
        }
        const __half* cX = hsm + buf*2*HBUF;
        const __half* cW = cX + HBUF;
        #pragma unroll
        for (int ks = 0; ks < 4; ks++) {
            int kb = ks * 16;
            uint32_t af[4][4], bf[4][2];
            #pragma unroll
            for (int mt = 0; mt < 4; mt++) {
                const __half* base = cX + (wm + mt*16 + arow)*HSTRIDE + kb + acol2;
                af[mt][0] = *(const uint32_t*)(base);
                af[mt][1] = *(const uint32_t*)(base + 8*HSTRIDE);
                af[mt][2] = *(const uint32_t*)(base + 8);
                af[mt][3] = *(const uint32_t*)(base + 8*HSTRIDE + 8);
            }
            #pragma unroll
            for (int nt = 0; nt < 4; nt++) {
                const __half* base = cW + (wn + nt*8 + arow)*HSTRIDE + kb + acol2;
                bf[nt][0] = *(const uint32_t*)(base);
                bf[nt][1] = *(const uint32_t*)(base + 8);
            }
            #pragma unroll
            for (int mt = 0; mt < 4; mt++)
                #pragma unroll
                for (int nt = 0; nt < 4; nt++)
                    mma16(acc[mt][nt], af[mt], bf[nt]);
        }
        if (kc + 1 < 2) { CPA_WAIT0(); }
        __syncthreads();
    }

    // epilogue: even lanes hold (p0,p1); odd lanes hold (g0,g1).
    float* a_s = (float*)hsm;        // [32][132] f32
    float* b_s = a_s + 32*132;
    int crow = lane >> 2, ccol = (lane & 3) * 2;
    #pragma unroll
    for (int mt = 0; mt < 4; mt++) {
        #pragma unroll
        for (int nt = 0; nt < 4; nt++) {
            float g0r1 = __shfl_xor_sync(0xffffffffu, acc[mt][nt][0], 1);
            float g1r1 = __shfl_xor_sync(0xffffffffu, acc[mt][nt][1], 1);
            float g0r2 = __shfl_xor_sync(0xffffffffu, acc[mt][nt][2], 1);
            float g1r2 = __shfl_xor_sync(0xffffffffu, acc[mt][nt][3], 1);
            if ((lane & 1) == 0) {
                int j  = wn + nt*8 + ccol;
                int cl = j >> 2;
                int r1 = wm + mt*16 + crow, r2 = r1 + 8;
                float mk1 = m_s[r1], mk2 = m_s[r2];
                a_s[cl*132 + r1] = acc[mt][nt][0] * mk1 * sigm(g0r1);
                b_s[cl*132 + r1] = acc[mt][nt][1] * mk1 * sigm(g1r1);
                a_s[cl*132 + r2] = acc[mt][nt][2] * mk2 * sigm(g0r2);
                b_s[cl*132 + r2] = acc[mt][nt][3] * mk2 * sigm(g1r2);
            }
        }
    }
    __syncthreads();
    int cb = cg * 32;
    #pragma unroll
    for (int it = 0; it < 2; it++) {
        int idx = tid + it*256;              // 0..511 : ch(0..31) x f8(0..15)
        int ch = idx >> 4, f8 = idx & 15;
        float4 alo = *(float4*)(a_s + ch*132 + f8*8);
        float4 ahi = *(float4*)(a_s + ch*132 + f8*8 + 4);
        float4 blo = *(float4*)(b_s + ch*132 + f8*8);
        float4 bhi = *(float4*)(b_s + ch*132 + f8*8 + 4);
        *(uint4*)(ga + (size_t)(cb+ch)*RTOT + i0 + f8*8) = h8pack(alo, ahi);
        *(uint4*)(gb + (size_t)(cb+ch)*RTOT + i0 + f8*8) = h8pack(blo, bhi);
    }
}

// ---------------------------------------------------------------- fp16 mma einsum (cp.async)
#define KC 64
#define NCHUNK (NTOK/KC)           // 12
#define DSMEM (4*HBUF*2)           // 73728 B

__global__ void __launch_bounds__(256, 2) k_einsum_mma()
{
    extern __shared__ __half hsm[];
    int c  = blockIdx.z;
    int i0 = blockIdx.y * 128;
    int j0 = blockIdx.x * 128;
    const __half* ga = (const __half*)g_ab;
    const __half* gb = ga + (size_t)CH*RTOT;
    const __half* A = ga + (size_t)c*RTOT + (size_t)i0*NTOK;
    const __half* B = gb + (size_t)c*RTOT + (size_t)j0*NTOK;
    float*        O = g_o + (size_t)c*RTOT;

    int tid = threadIdx.x, lane = tid & 31, warp = tid >> 5;
    int wm = (warp >> 2) * 64;
    int wn = (warp & 3) * 32;

    float acc[4][4][4];
    #pragma unroll
    for (int mt = 0; mt < 4; mt++)
        #pragma unroll
        for (int nt = 0; nt < 4; nt++)
            #pragma unroll
            for (int e = 0; e < 4; e++) acc[mt][nt][e] = 0.f;

    int rr = tid >> 3, q = tid & 7;

    {
        __half* dA = hsm;
        __half* dB = hsm + HBUF;
        #pragma unroll
        for (int l = 0; l < 4; l++) {
            int r = rr + l*32;
            cpa16(dA + r*HSTRIDE + q*8, A + (size_t)r*NTOK + q*8);
            cpa16(dB + r*HSTRIDE + q*8, B + (size_t)r*NTOK + q*8);
        }
        CPA_COMMIT(); CPA_WAIT0();
    }
    __syncthreads();

    int arow = lane >> 2, acol2 = (lane & 3) * 2;

    for (int kc = 0; kc < NCHUNK; kc++) {
        int buf = kc & 1;
        if (kc + 1 < NCHUNK) {
            __half* dA = hsm + (buf^1)*2*HBUF;
            __half* dB = dA + HBUF;
            const __half* As = A + (kc+1)*KC;
            const __half* Bs = B + (kc+1)*KC;
            #pragma unroll
            for (int l = 0; l < 4; l++) {
                int r = rr + l*32;
                cpa16(dA + r*HSTRIDE + q*8, As + (size_t)r*NTOK + q*8);
                cpa16(dB + r*HSTRIDE + q*8, Bs + (size_t)r*NTOK + q*8);
            }
            CPA_COMMIT();
        }
        const __half* cA = hsm + buf*2*HBUF;
        const __half* cB = cA + HBUF;
        #pragma unroll
        for (int ks = 0; ks < 4; ks++) {
            int kb = ks * 16;
            uint32_t af[4][4], bf[4][2];
            #pragma unroll
            for (int mt = 0; mt < 4; mt++) {
                const __half* base = cA + (wm + mt*16 + arow)*HSTRIDE + kb + acol2;
                af[mt][0] = *(const uint32_t*)(base);
                af[mt][1] = *(const uint32_t*)(base + 8*HSTRIDE);
                af[mt][2] = *(const uint32_t*)(base + 8);
                af[mt][3] = *(const uint32_t*)(base + 8*HSTRIDE + 8);
            }
            #pragma unroll
            for (int nt = 0; nt < 4; nt++) {
                const __half* base = cB + (wn + nt*8 + arow)*HSTRIDE + kb + acol2;
                bf[nt][0] = *(const uint32_t*)(base);
                bf[nt][1] = *(const uint32_t*)(base + 8);
            }
            #pragma unroll
            for (int mt = 0; mt < 4; mt++)
                #pragma unroll
                for (int nt = 0; nt < 4; nt++)
                    mma16(acc[mt][nt], af[mt], bf[nt]);
        }
        if (kc + 1 < NCHUNK) { CPA_WAIT0(); }
        __syncthreads();
    }

    int crow = lane >> 2, ccol = (lane & 3) * 2;
    #pragma unroll
    for (int mt = 0; mt < 4; mt++) {
        #pragma unroll
        for (int nt = 0; nt < 4; nt++) {
            float* d0 = O + (size_t)(i0 + wm + mt*16 + crow)*NTOK + j0 + wn + nt*8 + ccol;
            float2 v0; v0.x = acc[mt][nt][0]; v0.y = acc[mt][nt][1];
            float2 v1; v1.x = acc[mt][nt][2]; v1.y = acc[mt][nt][3];
            *(float2*)d0 = v0;
            *(float2*)(d0 + 8*NTOK) = v1;
        }
    }
}

// ---------------------------------------------------------------- LN2 + transpose (vectorized, fp16 out)
__global__ void k_ln2t(const float* __restrict__ w, const float* __restrict__ b)
{
    __shared__ float t[128*36];
    __shared__ float red[8][33];
    __shared__ float mu_s[32], rstd_s[32];
    __shared__ float w_s[128], b_s[128];
    int tid = threadIdx.x;
    size_t r0 = (size_t)blockIdx.x * 32;

    if (tid < 128) { w_s[tid] = w[tid]; b_s[tid] = b[tid]; }

    #pragma unroll
    for (int it = 0; it < 4; it++) {
        int idx = tid + it*256;            // 0..1023 : c(0..127) x rq(0..7)
        int c = idx >> 3, rq = idx & 7;
        *(float4*)(t + c*36 + rq*4) = *(const float4*)(g_o + (size_t)c*RTOT + r0 + rq*4);
    }
    __syncthreads();

    int rr = tid & 31, part = tid >> 5;
    float s = 0.f;
    #pragma unroll
    for (int k = 0; k < 16; k++) s += t[(part*16 + k)*36 + rr];
    red[part][rr] = s;
    __syncthreads();
    if (tid < 32) {
        float tot = 0.f;
        #pragma unroll
        for (int p = 0; p < 8; p++) tot += red[p][tid];
        mu_s[tid] = tot * (1.f/128.f);
    }
    __syncthreads();
    float mu = mu_s[rr], qv = 0.f;
    #pragma unroll
    for (int k = 0; k < 16; k++) {
        float d = t[(part*16 + k)*36 + rr] - mu; qv += d*d;
    }
    __syncthreads();
    red[part][rr] = qv;
    __syncthreads();
    if (tid < 32) {
        float tot = 0.f;
        #pragma unroll
        for (int p = 0; p < 8; p++) tot += red[p][tid];
        rstd_s[tid] = rsqrtf(tot * (1.f/128.f) + 1e-5f);
    }
    __syncthreads();

    float rstd = rstd_s[rr];
    mu = mu_s[rr];
    __half* u = (__half*)g_ab;   // ga/gb dead: reuse as fp16 u buffer [r][c]
    float f[16];
    #pragma unroll
    for (int k = 0; k < 16; k++) {
        int c = part*16 + k;
        f[k] = (t[c*36 + rr] - mu) * rstd * w_s[c] + b_s[c];
    }
    __half* dst = u + (r0 + rr)*CH + part*16;
    *(uint4*)(dst)     = h8pack(make_float4(f[0],f[1],f[2],f[3]),   make_float4(f[4],f[5],f[6],f[7]));
    *(uint4*)(dst + 8) = h8pack(make_float4(f[8],f[9],f[10],f[11]), make_float4(f[12],f[13],f[14],f[15]));
}

// ---------------------------------------------------------------- final (2 fused fp16 GEMMs, cp.async)
#define FN_SMEM (8*HBUF*2)   // 147456 B

__global__ void __launch_bounds__(256, 1) k_final_mma(float* __restrict__ out)
{
    extern __shared__ __half hsm[];
    int tid = threadIdx.x, lane = tid & 31, warp = tid >> 5;
    size_t i0 = (size_t)blockIdx.x * 128;
    const __half* U = (const __half*)g_ab + i0 * CH;
    const __half* X = g_xh + i0 * CH;
    const __half* Wo = g_wh + (size_t)512*CH;
    const __half* Wg = g_wh + (size_t)640*CH;

    int wm = (warp >> 2) * 64;
    int wn = (warp & 3) * 32;

    float accU[4][4][4], accX[4][4][4];
    #pragma unroll
    for (int mt = 0; mt < 4; mt++)
        #pragma unroll
        for (int nt = 0; nt < 4; nt++)
            #pragma unroll
            for (int e = 0; e < 4; e++) { accU[mt][nt][e] = 0.f; accX[mt][nt][e] = 0.f; }

    int rr = tid >> 3, q8 = tid & 7;

    // buffer b at hsm + b*4*HBUF; within: [U | X | Wo | Wg]
    {
        __half* d0 = hsm;
        #pragma unroll
        for (int l = 0; l < 4; l++) {
            int r = rr + l*32;
            cpa16(d0 + 0*HBUF + r*HSTRIDE + q8*8, U  + (size_t)r*CH + q8*8);
            cpa16(d0 + 1*HBUF + r*HSTRIDE + q8*8, X  + (size_t)r*CH + q8*8);
            cpa16(d0 + 2*HBUF + r*HSTRIDE + q8*8, Wo + (size_t)r*CH + q8*8);
            cpa16(d0 + 3*HBUF + r*HSTRIDE + q8*8, Wg + (size_t)r*CH + q8*8);
        }
        CPA_COMMIT(); CPA_WAIT0();
    }
    __syncthreads();

    int arow = lane >> 2, acol2 = (lane & 3) * 2;

    #pragma unroll
    for (int kc = 0; kc < 2; kc++) {
        int buf = kc & 1;
        if (kc + 1 < 2) {
            __half* d0 = hsm + (buf^1)*4*HBUF;
            #pragma unroll
            for (int l = 0; l < 4; l++) {
                int r = rr + l*32;
                cpa16(d0 + 0*HBUF + r*HSTRIDE + q8*8, U  + (size_t)r*CH + 64 + q8*8);
                cpa16(d0 + 1*HBUF + r*HSTRIDE + q8*8, X  + (size_t)r*CH + 64 + q8*8);
                cpa16(d0 + 2*HBUF + r*HSTRIDE + q8*8, Wo + (size_t)r*CH + 64 + q8*8);
                cpa16(d0 + 3*HBUF + r*HSTRIDE + q8*8, Wg + (size_t)r*CH + 64 + q8*8);
            }
            CPA_COMMIT();
        }
        const __half* cb = hsm + buf*4*HBUF;
        #pragma unroll
        for (int ks = 0; ks < 4; ks++) {
            int kb = ks * 16;
            uint32_t au[4][4], ax[4][4], bo[4][2], bg[4][2];
            #pragma unroll
            for (int mt = 0; mt < 4; mt++) {
                const __half* bu = cb + 0*HBUF + (wm + mt*16 + arow)*HSTRIDE + kb + acol2;
                au[mt][0] = *(const uint32_t*)(bu);
                au[mt][1] = *(const uint32_t*)(bu + 8*HSTRIDE);
                au[mt][2] = *(const uint32_t*)(bu + 8);
                au[mt][3] = *(const uint32_t*)(bu + 8*HSTRIDE + 8);
                const __half* bx = cb + 1*HBUF + (wm + mt*16 + arow)*HSTRIDE + kb + acol2;
                ax[mt][0] = *(const uint32_t*)(bx);
                ax[mt][1] = *(const uint32_t*)(bx + 8*HSTRIDE);
                ax[mt][2] = *(const uint32_t*)(bx + 8);
                ax[mt][3] = *(const uint32_t*)(bx + 8*HSTRIDE + 8);
            }
            #pragma unroll
            for (int nt = 0; nt < 4; nt++) {
                const __half* po = cb + 2*HBUF + (wn + nt*8 + arow)*HSTRIDE + kb + acol2;
                bo[nt][0] = *(const uint32_t*)(po);
                bo[nt][1] = *(const uint32_t*)(po + 8);
                const __half* pg = cb + 3*HBUF + (wn + nt*8 + arow)*HSTRIDE + kb + acol2;
                bg[nt][0] = *(const uint32_t*)(pg);
                bg[nt][1] = *(const uint32_t*)(pg + 8);
            }
            #pragma unroll
            for (int mt = 0; mt < 4; mt++)
                #pragma unroll
                for (int nt = 0; nt < 4; nt++) {
                    mma16(accU[mt][nt], au[mt], bo[nt]);
                    mma16(accX[mt][nt], ax[mt], bg[nt]);
                }
        }
        if (kc + 1 < 2) { CPA_WAIT0(); }
        __syncthreads();
    }

    int crow = lane >> 2, ccol = (lane & 3) * 2;
    #pragma unroll
    for (int mt = 0; mt < 4; mt++) {
        #pragma unroll
        for (int nt = 0; nt < 4; nt++) {
            size_t r1 = i0 + wm + mt*16 + crow;
            int col = wn + nt*8 + ccol;
            float2 v0, v1;
            v0.x = accU[mt][nt][0] * sigm(accX[mt][nt][0]);
            v0.y = accU[mt][nt][1] * sigm(accX[mt][nt][1]);
            v1.x = accU[mt][nt][2] * sigm(accX[mt][nt][2]);
            v1.y = accU[mt][nt][3] * sigm(accX[mt][nt][3]);
            *(float2*)(out + r1*CH + col) = v0;
            *(float2*)(out + (r1+8)*CH + col) = v1;
        }
    }
}

// ---------------------------------------------------------------- launch
extern "C" void kernel_launch(void* const* d_in, const int* in_sizes, int n_in,
                              void* d_out, int out_size)
{
    const float* pair     = (const float*)d_in[0];
    const float* mask     = (const float*)d_in[1];
    const float* ln1_w    = (const float*)d_in[2];
    const float* ln1_b    = (const float*)d_in[3];
    const float* proj_w   = (const float*)d_in[4];
    const float* gate_w   = (const float*)d_in[5];
    const float* ln2_w    = (const float*)d_in[6];
    const float* ln2_b    = (const float*)d_in[7];
    const float* out_w    = (const float*)d_in[8];
    const float* gating_w = (const float*)d_in[9];
    float* out = (float*)d_out;

    cudaFuncSetAttribute(k_projgate_mma, cudaFuncAttributeMaxDynamicSharedMemorySize, PG_SMEM);
    cudaFuncSetAttribute(k_einsum_mma,   cudaFuncAttributeMaxDynamicSharedMemorySize, DSMEM);
    cudaFuncSetAttribute(k_final_mma,    cudaFuncAttributeMaxDynamicSharedMemorySize, FN_SMEM);

    k_cvtw<<<48, 256>>>(proj_w, gate_w, out_w, gating_w);
    k_ln1<<<RTOT/8, 256>>>(pair, ln1_w, ln1_b);
    k_projgate_mma<<<dim3(4, RTOT/128), 256, PG_SMEM>>>(mask);
    k_einsum_mma<<<dim3(NTOK/128, NTOK/128, CH), 256, DSMEM>>>();
    k_ln2t<<<RTOT/32, 256>>>(ln2_w, ln2_b);
    k_final_mma<<<RTOT/128, 256, FN_SMEM>>>(out);
}

// round 11
// speedup vs baseline: 4.5678x; 1.0074x over previous
#include <cuda_runtime.h>
#include <cuda_fp16.h>
#include <math.h>
#include <stdint.h>

// TriangleMultiplication: N=768, C=128 — fp16 tensor-core pipeline + cp.async + ldmatrix
//   k_cvtw         : weights -> fp16 (g_wh: [512 pg-interleaved | 128 out_w | 128 gating_w])
//   k_ln1          : x = LN(pair)                            -> g_xh [r][c] fp16
//   k_projgate_mma : a,b = split((x@Wp^T)*mask*sig(x@Wg^T))  -> ga,gb [c][r] fp16
//   k_einsum_mma   : out_c = A_c @ B_c^T per channel (fp16)  -> g_o [c][i][j] f32
//   k_ln2t         : u = LN_c(out) transposed                -> u (= g_ab reuse) fp16 [r][c]
//   k_final_mma    : out = (u@Wo^T) * sig(x@Wgat^T) (fp16)   -> d_out f32

#define NTOK 768
#define CH   128
#define RTOT (NTOK*NTOK)   // 589824

__device__ __half g_xh[(size_t)RTOT*CH];
__device__ float  g_o[(size_t)CH*RTOT];
__device__ __align__(256) unsigned char g_ab[(size_t)CH*RTOT*4];  // 2x half[CH*RTOT]; later half u[RTOT*CH]
__device__ __half g_wh[768*CH];   // fp16 weights

__device__ __forceinline__ float sigm(float v){ return 1.f/(1.f+expf(-v)); }

// fp16 m16n8k16 warp MMA (f32 accum)
__device__ __forceinline__ void mma16(float* d, const uint32_t* a, const uint32_t* b){
    asm volatile(
        "mma.sync.aligned.m16n8k16.row.col.f32.f16.f16.f32 "
        "{%0,%1,%2,%3}, {%4,%5,%6,%7}, {%8,%9}, {%0,%1,%2,%3};"
        : "+f"(d[0]), "+f"(d[1]), "+f"(d[2]), "+f"(d[3])
        : "r"(a[0]), "r"(a[1]), "r"(a[2]), "r"(a[3]), "r"(b[0]), "r"(b[1]));
}

// ldmatrix x4 (non-transposed)
__device__ __forceinline__ void ldsm4(uint32_t* r, const __half* p){
    uint32_t a;
    asm("{ .reg .u64 t; cvta.to.shared.u64 t, %1; cvt.u32.u64 %0, t; }" : "=r"(a) : "l"(p));
    asm volatile("ldmatrix.sync.aligned.m8n8.x4.shared.b16 {%0,%1,%2,%3}, [%4];"
        : "=r"(r[0]), "=r"(r[1]), "=r"(r[2]), "=r"(r[3]) : "r"(a));
}

// pack 8 floats -> 8 halves = 16 bytes
__device__ __forceinline__ uint4 h8pack(float4 lo, float4 hi){
    uint4 r;
    __half2 a = __floats2half2_rn(lo.x, lo.y);
    __half2 b = __floats2half2_rn(lo.z, lo.w);
    __half2 c = __floats2half2_rn(hi.x, hi.y);
    __half2 d = __floats2half2_rn(hi.z, hi.w);
    r.x = *(uint32_t*)&a;
    r.y = *(uint32_t*)&b;
    r.z = *(uint32_t*)&c;
    r.w = *(uint32_t*)&d;
    return r;
}
__device__ __forceinline__ uint2 h4pack(float4 v){
    uint2 r;
    __half2 a = __floats2half2_rn(v.x, v.y);
    __half2 b = __floats2half2_rn(v.z, v.w);
    r.x = *(uint32_t*)&a;
    r.y = *(uint32_t*)&b;
    return r;
}

// 16B async copy, L2-resident (.cg)
__device__ __forceinline__ void cpa16(__half* dst, const __half* src){
    uint32_t s;
    asm("{ .reg .u64 t; cvta.to.shared.u64 t, %1; cvt.u32.u64 %0, t; }" : "=r"(s) : "l"(dst));
    asm volatile("cp.async.cg.shared.global [%0], [%1], 16;" :: "r"(s), "l"(src));
}
#define CPA_COMMIT() asm volatile("cp.async.commit_group;" ::: "memory")
#define CPA_WAIT0()  asm volatile("cp.async.wait_group 0;" ::: "memory")

#define HSTRIDE 72
#define HBUF (128*HSTRIDE)         // fp16 tile: 128 rows x 64 halves (stride 72)

// ldmatrix lane offsets (in halves) relative to tile base:
//   A frag (m16k16): rows (lane&7) + ((lane>>3)&1)*8, k-half (lane>>4)*8
//   B frag (2x n8k16): rows (lane&7) + (lane>>4)*8,  k-half ((lane>>3)&1)*8
__device__ __forceinline__ int a_lane_off(int lane){
    return ((lane & 7) + ((lane >> 3) & 1) * 8) * HSTRIDE + (lane >> 4) * 8;
}
__device__ __forceinline__ int b_lane_off(int lane){
    return ((lane & 7) + (lane >> 4) * 8) * HSTRIDE + ((lane >> 3) & 1) * 8;
}

// ---------------------------------------------------------------- weight convert
__global__ void k_cvtw(const float* __restrict__ projw, const float* __restrict__ gatew,
                       const float* __restrict__ outw,  const float* __restrict__ gatingw)
{
    int idx = blockIdx.x*256 + threadIdx.x;   // 768 rows x 16 vec8 = 12288
    int row = idx >> 4, q8 = idx & 15;
    const float* src;
    if (row < 512) {
        int c = row >> 2, q = row & 3;
        src = (q < 2) ? projw + (size_t)(2*c+q)*CH : gatew + (size_t)(2*c+q-2)*CH;
    } else if (row < 640) {
        src = outw + (size_t)(row-512)*CH;
    } else {
        src = gatingw + (size_t)(row-640)*CH;
    }
    float4 lo = *(const float4*)(src + q8*8);
    float4 hi = *(const float4*)(src + q8*8 + 4);
    *(uint4*)(g_wh + (size_t)row*CH + q8*8) = h8pack(lo, hi);
}

// ---------------------------------------------------------------- LN1 -> fp16 x
__global__ void k_ln1(const float* __restrict__ pair,
                      const float* __restrict__ w,
                      const float* __restrict__ b)
{
    int warp = threadIdx.x >> 5, lane = threadIdx.x & 31;
    size_t r = (size_t)blockIdx.x * 8 + warp;
    const float4* src = (const float4*)(pair + r * CH);
    float4 v = src[lane];
    float s = v.x + v.y + v.z + v.w;
    #pragma unroll
    for (int o = 16; o; o >>= 1) s += __shfl_xor_sync(0xffffffffu, s, o);
    float mu = s * (1.f/128.f);
    float dx = v.x-mu, dy = v.y-mu, dz = v.z-mu, dw = v.w-mu;
    float q = dx*dx + dy*dy + dz*dz + dw*dw;
    #pragma unroll
    for (int o = 16; o; o >>= 1) q += __shfl_xor_sync(0xffffffffu, q, o);
    float rstd = rsqrtf(q * (1.f/128.f) + 1e-5f);
    float4 wv = ((const float4*)w)[lane];
    float4 bv = ((const float4*)b)[lane];
    float4 o4;
    o4.x = dx*rstd*wv.x + bv.x;
    o4.y = dy*rstd*wv.y + bv.y;
    o4.z = dz*rstd*wv.z + bv.z;
    o4.w = dw*rstd*wv.w + bv.w;
    *(uint2*)(g_xh + r * CH + lane*4) = h4pack(o4);
}

// ---------------------------------------------------------------- proj+gate (fp16 mma + cp.async + ldmatrix)
#define PG_SMEM (4*HBUF*2)   // 73728 B

__global__ void __launch_bounds__(256, 2) k_projgate_mma(const float* __restrict__ mask)
{
    extern __shared__ __half hsm[];
    __shared__ float m_s[128];
    int tid = threadIdx.x, lane = tid & 31, warp = tid >> 5;
    int cg = blockIdx.x;
    size_t i0 = (size_t)blockIdx.y * 128;
    const __half* A = g_xh + i0 * CH;
    __half* ga = (__half*)g_ab;
    __half* gb = ga + (size_t)CH*RTOT;

    if (tid < 128) m_s[tid] = mask[(int)(i0 % NTOK) + tid];

    int wm = (warp >> 2) * 64;
    int wn = (warp & 3) * 32;

    float acc[4][4][4];
    #pragma unroll
    for (int mt = 0; mt < 4; mt++)
        #pragma unroll
        for (int nt = 0; nt < 4; nt++)
            #pragma unroll
            for (int e = 0; e < 4; e++) acc[mt][nt][e] = 0.f;

    int rr = tid >> 3, q8 = tid & 7;
    const __half* W = g_wh + (size_t)(cg*128) * CH;

    {
        __half* dX = hsm;
        __half* dW = hsm + HBUF;
        #pragma unroll
        for (int l = 0; l < 4; l++) {
            int r = rr + l*32;
            cpa16(dX + r*HSTRIDE + q8*8, A + (size_t)r*CH + q8*8);
            cpa16(dW + r*HSTRIDE + q8*8, W + (size_t)r*CH + q8*8);
        }
        CPA_COMMIT(); CPA_WAIT0();
    }
    __syncthreads();

    int ao = wm*HSTRIDE + a_lane_off(lane);
    int bo = wn*HSTRIDE + b_lane_off(lane);

    #pragma unroll
    for (int kc = 0; kc < 2; kc++) {
        int buf = kc & 1;
        if (kc + 1 < 2) {
            __half* dX = hsm + (buf^1)*2*HBUF;
            __half* dW = dX + HBUF;
            #pragma unroll
            for (int l = 0; l < 4; l++) {
                int r = rr + l*32;
                cpa16(dX + r*HSTRIDE + q8*8, A + (size_t)r*CH + 64 + q8*8);
                cpa16(dW + r*HSTRIDE + q8*8, W + (size_t)r*CH + 64 + q8*8);
            }
            CPA_COMMIT();
        }
        const __half* cX = hsm + buf*2*HBUF;
        const __half* cW = cX + HBUF;
        #pragma unroll
        for (int ks = 0; ks < 4; ks++) {
            int kb = ks * 16;
            uint32_t af[4][4], bf[2][4];
            #pragma unroll
            for (int mt = 0; mt < 4; mt++) ldsm4(af[mt], cX + ao + mt*16*HSTRIDE + kb);
            #pragma unroll
            for (int np = 0; np < 2; np++) ldsm4(bf[np], cW + bo + np*16*HSTRIDE + kb);
            #pragma unroll
            for (int mt = 0; mt < 4; mt++)
                #pragma unroll
                for (int nt = 0; nt < 4; nt++)
                    mma16(acc[mt][nt], af[mt], &bf[nt>>1][(nt&1)*2]);
        }
        if (kc + 1 < 2) { CPA_WAIT0(); }
        __syncthreads();
    }

    // epilogue: even lanes hold (p0,p1); odd lanes hold (g0,g1).
    float* a_s = (float*)hsm;        // [32][132] f32
    float* b_s = a_s + 32*132;
    int crow = lane >> 2, ccol = (lane & 3) * 2;
    #pragma unroll
    for (int mt = 0; mt < 4; mt++) {
        #pragma unroll
        for (int nt = 0; nt < 4; nt++) {
            float g0r1 = __shfl_xor_sync(0xffffffffu, acc[mt][nt][0], 1);
            float g1r1 = __shfl_xor_sync(0xffffffffu, acc[mt][nt][1], 1);
            float g0r2 = __shfl_xor_sync(0xffffffffu, acc[mt][nt][2], 1);
            float g1r2 = __shfl_xor_sync(0xffffffffu, acc[mt][nt][3], 1);
            if ((lane & 1) == 0) {
                int j  = wn + nt*8 + ccol;
                int cl = j >> 2;
                int r1 = wm + mt*16 + crow, r2 = r1 + 8;
                float mk1 = m_s[r1], mk2 = m_s[r2];
                a_s[cl*132 + r1] = acc[mt][nt][0] * mk1 * sigm(g0r1);
                b_s[cl*132 + r1] = acc[mt][nt][1] * mk1 * sigm(g1r1);
                a_s[cl*132 + r2] = acc[mt][nt][2] * mk2 * sigm(g0r2);
                b_s[cl*132 + r2] = acc[mt][nt][3] * mk2 * sigm(g1r2);
            }
        }
    }
    __syncthreads();
    int cb = cg * 32;
    #pragma unroll
    for (int it = 0; it < 2; it++) {
        int idx = tid + it*256;              // 0..511 : ch(0..31) x f8(0..15)
        int ch = idx >> 4, f8 = idx & 15;
        float4 alo = *(float4*)(a_s + ch*132 + f8*8);
        float4 ahi = *(float4*)(a_s + ch*132 + f8*8 + 4);
        float4 blo = *(float4*)(b_s + ch*132 + f8*8);
        float4 bhi = *(float4*)(b_s + ch*132 + f8*8 + 4);
        *(uint4*)(ga + (size_t)(cb+ch)*RTOT + i0 + f8*8) = h8pack(alo, ahi);
        *(uint4*)(gb + (size_t)(cb+ch)*RTOT + i0 + f8*8) = h8pack(blo, bhi);
    }
}

// ---------------------------------------------------------------- fp16 mma einsum (cp.async + ldmatrix)
#define KC 64
#define NCHUNK (NTOK/KC)           // 12
#define DSMEM (4*HBUF*2)           // 73728 B

__global__ void __launch_bounds__(256, 2) k_einsum_mma()
{
    extern __shared__ __half hsm[];
    int c  = blockIdx.z;
    int i0 = blockIdx.y * 128;
    int j0 = blockIdx.x * 128;
    const __half* ga = (const __half*)g_ab;
    const __half* gb = ga + (size_t)CH*RTOT;
    const __half* A = ga + (size_t)c*RTOT + (size_t)i0*NTOK;
    const __half* B = gb + (size_t)c*RTOT + (size_t)j0*NTOK;
    float*        O = g_o + (size_t)c*RTOT;

    int tid = threadIdx.x, lane = tid & 31, warp = tid >> 5;
    int wm = (warp >> 2) * 64;
    int wn = (warp & 3) * 32;

    float acc[4][4][4];
    #pragma unroll
    for (int mt = 0; mt < 4; mt++)
        #pragma unroll
        for (int nt = 0; nt < 4; nt++)
            #pragma unroll
            for (int e = 0; e < 4; e++) acc[mt][nt][e] = 0.f;

    int rr = tid >> 3, q = tid & 7;

    {
        __half* dA = hsm;
        __half* dB = hsm + HBUF;
        #pragma unroll
        for (int l = 0; l < 4; l++) {
            int r = rr + l*32;
            cpa16(dA + r*HSTRIDE + q*8, A + (size_t)r*NTOK + q*8);
            cpa16(dB + r*HSTRIDE + q*8, B + (size_t)r*NTOK + q*8);
        }
        CPA_COMMIT(); CPA_WAIT0();
    }
    __syncthreads();

    int ao = wm*HSTRIDE + a_lane_off(lane);
    int bo = wn*HSTRIDE + b_lane_off(lane);

    for (int kc = 0; kc < NCHUNK; kc++) {
        int buf = kc & 1;
        if (kc + 1 < NCHUNK) {
            __half* dA = hsm + (buf^1)*2*HBUF;
            __half* dB = dA + HBUF;
            const __half* As = A + (kc+1)*KC;
            const __half* Bs = B + (kc+1)*KC;
            #pragma unroll
            for (int l = 0; l < 4; l++) {
                int r = rr + l*32;
                cpa16(dA + r*HSTRIDE + q*8, As + (size_t)r*NTOK + q*8);
                cpa16(dB + r*HSTRIDE + q*8, Bs + (size_t)r*NTOK + q*8);
            }
            CPA_COMMIT();
        }
        const __half* cA = hsm + buf*2*HBUF;
        const __half* cB = cA + HBUF;
        #pragma unroll
        for (int ks = 0; ks < 4; ks++) {
            int kb = ks * 16;
            uint32_t af[4][4], bf[2][4];
            #pragma unroll
            for (int mt = 0; mt < 4; mt++) ldsm4(af[mt], cA + ao + mt*16*HSTRIDE + kb);
            #pragma unroll
            for (int np = 0; np < 2; np++) ldsm4(bf[np], cB + bo + np*16*HSTRIDE + kb);
            #pragma unroll
            for (int mt = 0; mt < 4; mt++)
                #pragma unroll
                for (int nt = 0; nt < 4; nt++)
                    mma16(acc[mt][nt], af[mt], &bf[nt>>1][(nt&1)*2]);
        }
        if (kc + 1 < NCHUNK) { CPA_WAIT0(); }
        __syncthreads();
    }

    int crow = lane >> 2, ccol = (lane & 3) * 2;
    #pragma unroll
    for (int mt = 0; mt < 4; mt++) {
        #pragma unroll
        for (int nt = 0; nt < 4; nt++) {
            float* d0 = O + (size_t)(i0 + wm + mt*16 + crow)*NTOK + j0 + wn + nt*8 + ccol;
            float2 v0; v0.x = acc[mt][nt][0]; v0.y = acc[mt][nt][1];
            float2 v1; v1.x = acc[mt][nt][2]; v1.y = acc[mt][nt][3];
            *(float2*)d0 = v0;
            *(float2*)(d0 + 8*NTOK) = v1;
        }
    }
}

// ---------------------------------------------------------------- LN2 + transpose (vectorized, fp16 out)
__global__ void k_ln2t(const float* __restrict__ w, const float* __restrict__ b)
{
    __shared__ float t[128*36];
    __shared__ float red[8][33];
    __shared__ float mu_s[32], rstd_s[32];
    __shared__ float w_s[128], b_s[128];
    int tid = threadIdx.x;
    size_t r0 = (size_t)blockIdx.x * 32;

    if (tid < 128) { w_s[tid] = w[tid]; b_s[tid] = b[tid]; }

    #pragma unroll
    for (int it = 0; it < 4; it++) {
        int idx = tid + it*256;            // 0..1023 : c(0..127) x rq(0..7)
        int c = idx >> 3, rq = idx & 7;
        *(float4*)(t + c*36 + rq*4) = *(const float4*)(g_o + (size_t)c*RTOT + r0 + rq*4);
    }
    __syncthreads();

    int rr = tid & 31, part = tid >> 5;
    float s = 0.f;
    #pragma unroll
    for (int k = 0; k < 16; k++) s += t[(part*16 + k)*36 + rr];
    red[part][rr] = s;
    __syncthreads();
    if (tid < 32) {
        float tot = 0.f;
        #pragma unroll
        for (int p = 0; p < 8; p++) tot += red[p][tid];
        mu_s[tid] = tot * (1.f/128.f);
    }
    __syncthreads();
    float mu = mu_s[rr], qv = 0.f;
    #pragma unroll
    for (int k = 0; k < 16; k++) {
        float d = t[(part*16 + k)*36 + rr] - mu; qv += d*d;
    }
    __syncthreads();
    red[part][rr] = qv;
    __syncthreads();
    if (tid < 32) {
        float tot = 0.f;
        #pragma unroll
        for (int p = 0; p < 8; p++) tot += red[p][tid];
        rstd_s[tid] = rsqrtf(tot * (1.f/128.f) + 1e-5f);
    }
    __syncthreads();

    float rstd = rstd_s[rr];
    mu = mu_s[rr];
    __half* u = (__half*)g_ab;   // ga/gb dead: reuse as fp16 u buffer [r][c]
    float f[16];
    #pragma unroll
    for (int k = 0; k < 16; k++) {
        int c = part*16 + k;
        f[k] = (t[c*36 + rr] - mu) * rstd * w_s[c] + b_s[c];
    }
    __half* dst = u + (r0 + rr)*CH + part*16;
    *(uint4*)(dst)     = h8pack(make_float4(f[0],f[1],f[2],f[3]),   make_float4(f[4],f[5],f[6],f[7]));
    *(uint4*)(dst + 8) = h8pack(make_float4(f[8],f[9],f[10],f[11]), make_float4(f[12],f[13],f[14],f[15]));
}

// ---------------------------------------------------------------- final (2 fused fp16 GEMMs, cp.async + ldmatrix)
#define FN_SMEM (8*HBUF*2)   // 147456 B

__global__ void __launch_bounds__(256, 1) k_final_mma(float* __restrict__ out)
{
    extern __shared__ __half hsm[];
    int tid = threadIdx.x, lane = tid & 31, warp = tid >> 5;
    size_t i0 = (size_t)blockIdx.x * 128;
    const __half* U = (const __half*)g_ab + i0 * CH;
    const __half* X = g_xh + i0 * CH;
    const __half* Wo = g_wh + (size_t)512*CH;
    const __half* Wg = g_wh + (size_t)640*CH;

    int wm = (warp >> 2) * 64;
    int wn = (warp & 3) * 32;

    float accU[4][4][4], accX[4][4][4];
    #pragma unroll
    for (int mt = 0; mt < 4; mt++)
        #pragma unroll
        for (int nt = 0; nt < 4; nt++)
            #pragma unroll
            for (int e = 0; e < 4; e++) { accU[mt][nt][e] = 0.f; accX[mt][nt][e] = 0.f; }

    int rr = tid >> 3, q8 = tid & 7;

    {
        __half* d0 = hsm;
        #pragma unroll
        for (int l = 0; l < 4; l++) {
            int r = rr + l*32;
            cpa16(d0 + 0*HBUF + r*HSTRIDE + q8*8, U  + (size_t)r*CH + q8*8);
            cpa16(d0 + 1*HBUF + r*HSTRIDE + q8*8, X  + (size_t)r*CH + q8*8);
            cpa16(d0 + 2*HBUF + r*HSTRIDE + q8*8, Wo + (size_t)r*CH + q8*8);
            cpa16(d0 + 3*HBUF + r*HSTRIDE + q8*8, Wg + (size_t)r*CH + q8*8);
        }
        CPA_COMMIT(); CPA_WAIT0();
    }
    __syncthreads();

    int ao = wm*HSTRIDE + a_lane_off(lane);
    int bo = wn*HSTRIDE + b_lane_off(lane);

    #pragma unroll
    for (int kc = 0; kc < 2; kc++) {
        int buf = kc & 1;
        if (kc + 1 < 2) {
            __half* d0 = hsm + (buf^1)*4*HBUF;
            #pragma unroll
            for (int l = 0; l < 4; l++) {
                int r = rr + l*32;
                cpa16(d0 + 0*HBUF + r*HSTRIDE + q8*8, U  + (size_t)r*CH + 64 + q8*8);
                cpa16(d0 + 1*HBUF + r*HSTRIDE + q8*8, X  + (size_t)r*CH + 64 + q8*8);
                cpa16(d0 + 2*HBUF + r*HSTRIDE + q8*8, Wo + (size_t)r*CH + 64 + q8*8);
                cpa16(d0 + 3*HBUF + r*HSTRIDE + q8*8, Wg + (size_t)r*CH + 64 + q8*8);
            }
            CPA_COMMIT();
        }
        const __half* cb = hsm + buf*4*HBUF;
        #pragma unroll
        for (int ks = 0; ks < 4; ks++) {
            int kb = ks * 16;
            uint32_t au[4][4], ax[4][4], bo2[2][4], bg2[2][4];
            #pragma unroll
            for (int mt = 0; mt < 4; mt++) {
                ldsm4(au[mt], cb + 0*HBUF + ao + mt*16*HSTRIDE + kb);
                ldsm4(ax[mt], cb + 1*HBUF + ao + mt*16*HSTRIDE + kb);
            }
            #pragma unroll
            for (int np = 0; np < 2; np++) {
                ldsm4(bo2[np], cb + 2*HBUF + bo + np*16*HSTRIDE + kb);
                ldsm4(bg2[np], cb + 3*HBUF + bo + np*16*HSTRIDE + kb);
            }
            #pragma unroll
            for (int mt = 0; mt < 4; mt++)
                #pragma unroll
                for (int nt = 0; nt < 4; nt++) {
                    mma16(accU[mt][nt], au[mt], &bo2[nt>>1][(nt&1)*2]);
                    mma16(accX[mt][nt], ax[mt], &bg2[nt>>1][(nt&1)*2]);
                }
        }
        if (kc + 1 < 2) { CPA_WAIT0(); }
        __syncthreads();
    }

    int crow = lane >> 2, ccol = (lane & 3) * 2;
    #pragma unroll
    for (int mt = 0; mt < 4; mt++) {
        #pragma unroll
        for (int nt = 0; nt < 4; nt++) {
            size_t r1 = i0 + wm + mt*16 + crow;
            int col = wn + nt*8 + ccol;
            float2 v0, v1;
            v0.x = accU[mt][nt][0] * sigm(accX[mt][nt][0]);
            v0.y = accU[mt][nt][1] * sigm(accX[mt][nt][1]);
            v1.x = accU[mt][nt][2] * sigm(accX[mt][nt][2]);
            v1.y = accU[mt][nt][3] * sigm(accX[mt][nt][3]);
            *(float2*)(out + r1*CH + col) = v0;
            *(float2*)(out + (r1+8)*CH + col) = v1;
        }
    }
}

// ---------------------------------------------------------------- launch
extern "C" void kernel_launch(void* const* d_in, const int* in_sizes, int n_in,
                              void* d_out, int out_size)
{
    const float* pair     = (const float*)d_in[0];
    const float* mask     = (const float*)d_in[1];
    const float* ln1_w    = (const float*)d_in[2];
    const float* ln1_b    = (const float*)d_in[3];
    const float* proj_w   = (const float*)d_in[4];
    const float* gate_w   = (const float*)d_in[5];
    const float* ln2_w    = (const float*)d_in[6];
    const float* ln2_b    = (const float*)d_in[7];
    const float* out_w    = (const float*)d_in[8];
    const float* gating_w = (const float*)d_in[9];
    float* out = (float*)d_out;

    cudaFuncSetAttribute(k_projgate_mma, cudaFuncAttributeMaxDynamicSharedMemorySize, PG_SMEM);
    cudaFuncSetAttribute(k_einsum_mma,   cudaFuncAttributeMaxDynamicSharedMemorySize, DSMEM);
    cudaFuncSetAttribute(k_final_mma,    cudaFuncAttributeMaxDynamicSharedMemorySize, FN_SMEM);

    k_cvtw<<<48, 256>>>(proj_w, gate_w, out_w, gating_w);
    k_ln1<<<RTOT/8, 256>>>(pair, ln1_w, ln1_b);
    k_projgate_mma<<<dim3(4, RTOT/128), 256, PG_SMEM>>>(mask);
    k_einsum_mma<<<dim3(NTOK/128, NTOK/128, CH), 256, DSMEM>>>();
    k_ln2t<<<RTOT/32, 256>>>(ln2_w, ln2_b);
    k_final_mma<<<RTOT/128, 256, FN_SMEM>>>(out);
}